// round 1
// baseline (speedup 1.0000x reference)
#include <cuda_runtime.h>
#include <math.h>

#define BB 2
#define CC 64
#define HH 128
#define WW 160
#define DD 16
#define VV 4
#define NV 9
#define HWP (HH*WW)

// ---------------- scratch (static device memory; no allocation) ----------------
__device__ __align__(16) float g_srcT[(size_t)VV*BB*HWP*CC]; // [v*B+b][hw][c]
__device__ __align__(16) float g_refT[(size_t)BB*HWP*CC];    // [b][hw][c]
__device__ float g_proj[VV*BB*12];                           // rot(3x3)+trans per row: r0 r1 r2 t
__device__ __align__(16) float g_s[(size_t)BB*HWP*DD];       // s channels-last [b][hw][d]

// fold BN scale 1/sqrt(1+1e-5)
#define BNS 0.9999950000374997f

// ---------------- K0: transpose [C,HW] -> [HW,C] for src(8 imgs) + ref(2 imgs) ----------------
__global__ void k_transpose(const float* __restrict__ ref, const float* __restrict__ src) {
    __shared__ float tile[64][65];
    int img = blockIdx.y;          // 0..7 = src v*B+b, 8..9 = ref b
    int hw0 = blockIdx.x * 64;
    const float* in;
    float* out;
    if (img < VV*BB) { in = src + (size_t)img*CC*HWP; out = g_srcT + (size_t)img*HWP*CC; }
    else            { int b = img - VV*BB; in = ref + (size_t)b*CC*HWP; out = g_refT + (size_t)b*HWP*CC; }
    for (int k = threadIdx.x; k < 64*64; k += blockDim.x) {
        int c = k >> 6, hwl = k & 63;
        tile[hwl][c] = in[(size_t)c*HWP + hw0 + hwl];
    }
    __syncthreads();
    for (int k = threadIdx.x; k < 64*64; k += blockDim.x) {
        int hwl = k >> 6, c = k & 63;
        out[(size_t)(hw0+hwl)*CC + c] = tile[hwl][c];
    }
}

// ---------------- K1: proj = src_proj @ inv(ref_proj), keep rows 0..2 ----------------
__global__ void k_proj(const float* __restrict__ ref_proj, const float* __restrict__ src_projs) {
    int t = threadIdx.x;
    if (t >= VV*BB) return;
    int v = t / BB, b = t % BB;
    float a[4][4], inv[4][4];
    #pragma unroll
    for (int i = 0; i < 4; i++)
        #pragma unroll
        for (int j = 0; j < 4; j++) {
            a[i][j] = ref_proj[b*16 + i*4 + j];
            inv[i][j] = (i == j) ? 1.f : 0.f;
        }
    // Gauss-Jordan with partial pivoting
    for (int col = 0; col < 4; col++) {
        int piv = col; float best = fabsf(a[col][col]);
        for (int r = col+1; r < 4; r++) { float av = fabsf(a[r][col]); if (av > best) { best = av; piv = r; } }
        if (piv != col) {
            for (int j = 0; j < 4; j++) {
                float tm = a[col][j]; a[col][j] = a[piv][j]; a[piv][j] = tm;
                tm = inv[col][j]; inv[col][j] = inv[piv][j]; inv[piv][j] = tm;
            }
        }
        float dsc = 1.f / a[col][col];
        for (int j = 0; j < 4; j++) { a[col][j] *= dsc; inv[col][j] *= dsc; }
        for (int r = 0; r < 4; r++) {
            if (r == col) continue;
            float f = a[r][col];
            for (int j = 0; j < 4; j++) { a[r][j] -= f*a[col][j]; inv[r][j] -= f*inv[col][j]; }
        }
    }
    const float* s = src_projs + (size_t)(v*BB + b)*16;
    float* o = g_proj + (v*BB + b)*12;
    for (int i = 0; i < 3; i++) {
        for (int j = 0; j < 4; j++) {
            float acc = 0.f;
            for (int k = 0; k < 4; k++) acc += s[i*4 + k] * inv[k][j];
            o[i*4 + j] = acc;
        }
    }
}

// ---------------- small MLP (8 -> 16 -> 8 -> 1), weights in shared ----------------
// layout: [0:128) w0 (16x8), [128:144) gs0, [144:160) b0, [160:288) w1 (8x16),
//         [288:296) gs1, [296:304) b1, [304:312) w2, [312] c2b
__device__ __forceinline__ float mlp8(const float* __restrict__ sw, const float in8[8]) {
    float h1[16];
    #pragma unroll
    for (int j = 0; j < 16; j++) {
        float a = 0.f;
        #pragma unroll
        for (int g = 0; g < 8; g++) a += sw[j*8 + g] * in8[g];
        h1[j] = fmaxf(0.f, a * sw[128 + j] + sw[144 + j]);
    }
    float o = sw[312];
    #pragma unroll
    for (int k = 0; k < 8; k++) {
        float a = 0.f;
        #pragma unroll
        for (int j = 0; j < 16; j++) a += sw[160 + k*16 + j] * h1[j];
        float h2 = fmaxf(0.f, a * sw[288 + k] + sw[296 + k]);
        o += sw[304 + k] * h2;
    }
    return o;
}

// ---------------- K2: warp + group correlation + pixelwise net + similarity net ----------------
// block = 128 threads = 8 pixels, 16 lanes per pixel (4 channels each)
__global__ void __launch_bounds__(128)
k_main(const float* __restrict__ depth_sample,
       const float* __restrict__ pw_w0, const float* __restrict__ pw_g0, const float* __restrict__ pw_b0,
       const float* __restrict__ pw_w1, const float* __restrict__ pw_g1, const float* __restrict__ pw_b1,
       const float* __restrict__ pw_w2, const float* __restrict__ pw_c2b,
       const float* __restrict__ sn_w0, const float* __restrict__ sn_g0, const float* __restrict__ sn_b0,
       const float* __restrict__ sn_w1, const float* __restrict__ sn_g1, const float* __restrict__ sn_b1,
       const float* __restrict__ sn_w2, const float* __restrict__ sn_c2b,
       float* __restrict__ out_vw) {
    __shared__ float sw[2][320];
    __shared__ float simv[8][16][8];
    __shared__ float simsum[8][16][8];
    __shared__ float wsum[8];

    int tid = threadIdx.x;
    for (int i = tid; i < 128; i += 128) {
        sw[0][i] = pw_w0[i];       sw[1][i] = sn_w0[i];
        sw[0][160 + i] = pw_w1[i]; sw[1][160 + i] = sn_w1[i];
    }
    if (tid < 16) {
        sw[0][128 + tid] = pw_g0[tid] * BNS; sw[0][144 + tid] = pw_b0[tid];
        sw[1][128 + tid] = sn_g0[tid] * BNS; sw[1][144 + tid] = sn_b0[tid];
    }
    if (tid < 8) {
        sw[0][288 + tid] = pw_g1[tid] * BNS; sw[0][296 + tid] = pw_b1[tid]; sw[0][304 + tid] = pw_w2[tid];
        sw[1][288 + tid] = sn_g1[tid] * BNS; sw[1][296 + tid] = sn_b1[tid]; sw[1][304 + tid] = sn_w2[tid];
    }
    if (tid == 0) { sw[0][312] = pw_c2b[0]; sw[1][312] = sn_c2b[0]; }
    __syncthreads();

    int pix  = tid >> 4;
    int lane = tid & 15;
    int p = blockIdx.x * 8 + pix;        // global pixel 0..B*HW-1
    int b  = p / HWP;
    int hw = p - b * HWP;
    int h = hw / WW, w = hw - h * WW;
    float wf = (float)w, hf = (float)h;

    const float4 rf = *(const float4*)(g_refT + (size_t)p*CC + lane*4);

    #pragma unroll
    for (int g = 0; g < 8; g++) simsum[pix][lane][g] = 0.f;
    if (lane == 0) wsum[pix] = 0.f;
    __syncwarp();

    const float* dsB = depth_sample + (size_t)b*DD*HWP + hw;

    for (int v = 0; v < VV; v++) {
        const float* M = g_proj + (v*BB + b)*12;
        float r00=M[0], r01=M[1], r02=M[2], t0=M[3];
        float r10=M[4], r11=M[5], r12=M[6], t1=M[7];
        float r20=M[8], r21=M[9], r22=M[10], t2=M[11];
        float rx = r00*wf + r01*hf + r02;
        float ry = r10*wf + r11*hf + r12;
        float rz = r20*wf + r21*hf + r22;
        const float* srcB = g_srcT + (size_t)(v*BB + b)*HWP*CC;

        #pragma unroll 2
        for (int d = 0; d < DD; d++) {
            float dep = __ldg(dsB + (size_t)d*HWP);
            float px = rx*dep + t0, py = ry*dep + t1, pz = rz*dep + t2;
            if (pz <= 0.001f) { px = (float)WW; py = (float)HH; pz = 1.f; }
            float rinv = 1.f / pz;
            float ix = px * rinv, iy = py * rinv;
            float x0f = floorf(ix), y0f = floorf(iy);
            float fx = ix - x0f, fy = iy - y0f;
            int x0 = (int)x0f, y0 = (int)y0f;
            int x1 = x0 + 1, y1 = y0 + 1;
            bool vx0 = (x0 >= 0) & (x0 < WW);
            bool vx1 = (x1 >= 0) & (x1 < WW);
            bool vy0 = (y0 >= 0) & (y0 < HH);
            bool vy1 = (y1 >= 0) & (y1 < HH);
            float w00 = (1.f-fx)*(1.f-fy) * (float)(vx0 && vy0);
            float w01 = fx*(1.f-fy)       * (float)(vx1 && vy0);
            float w10 = (1.f-fx)*fy       * (float)(vx0 && vy1);
            float w11 = fx*fy             * (float)(vx1 && vy1);
            int xc0 = min(max(x0, 0), WW-1), xc1 = min(max(x1, 0), WW-1);
            int yc0 = min(max(y0, 0), HH-1), yc1 = min(max(y1, 0), HH-1);
            const float4* p00 = (const float4*)(srcB + (size_t)(yc0*WW + xc0)*CC) + lane;
            const float4* p01 = (const float4*)(srcB + (size_t)(yc0*WW + xc1)*CC) + lane;
            const float4* p10 = (const float4*)(srcB + (size_t)(yc1*WW + xc0)*CC) + lane;
            const float4* p11 = (const float4*)(srcB + (size_t)(yc1*WW + xc1)*CC) + lane;
            float4 t00 = __ldg(p00), t01 = __ldg(p01), t10 = __ldg(p10), t11 = __ldg(p11);
            float ax = w00*t00.x + w01*t01.x + w10*t10.x + w11*t11.x;
            float ay = w00*t00.y + w01*t01.y + w10*t10.y + w11*t11.y;
            float az = w00*t00.z + w01*t01.z + w10*t10.z + w11*t11.z;
            float aw = w00*t00.w + w01*t01.w + w10*t10.w + w11*t11.w;
            float part = ax*rf.x + ay*rf.y + az*rf.z + aw*rf.w;
            part += __shfl_xor_sync(0xffffffffu, part, 1);
            if (!(lane & 1)) simv[pix][d][lane >> 1] = part * 0.125f;
        }
        __syncwarp();

        // each lane owns depth d = lane
        float in8[8];
        #pragma unroll
        for (int g = 0; g < 8; g++) in8[g] = simv[pix][lane][g];
        float o = mlp8(sw[0], in8);
        float vwv = 1.f / (1.f + expf(-o));
        #pragma unroll
        for (int k = 8; k >= 1; k >>= 1)
            vwv = fmaxf(vwv, __shfl_xor_sync(0xffffffffu, vwv, k, 16));
        #pragma unroll
        for (int g = 0; g < 8; g++) simsum[pix][lane][g] += in8[g] * vwv;
        if (lane == 0) {
            wsum[pix] += vwv;
            out_vw[((size_t)b*VV + v)*HWP + hw] = vwv;
        }
        __syncwarp();
    }

    float rws = 1.f / wsum[pix];
    float in8[8];
    #pragma unroll
    for (int g = 0; g < 8; g++) in8[g] = simsum[pix][lane][g] * rws;
    float sval = mlp8(sw[1], in8);
    g_s[(size_t)p*DD + lane] = sval;
}

// ---------------- K3: grid-sample s (border clamp) + NN aggregation + softmax + depth ----------------
__global__ void __launch_bounds__(128)
k_final(const float* __restrict__ grid, const float* __restrict__ weight,
        const float* __restrict__ depth_sample, const int* __restrict__ is_inverse,
        float* __restrict__ out_depth, float* __restrict__ out_score) {
    int p = blockIdx.x * blockDim.x + threadIdx.x;
    if (p >= BB*HWP) return;
    int b  = p / HWP;
    int hw = p - b * HWP;
    int h = hw / WW, w = hw - h * WW;

    float agg[DD];
    #pragma unroll
    for (int d = 0; d < DD; d++) agg[d] = 0.f;

    for (int n = 0; n < NV; n++) {
        const float* gp = grid + (((size_t)b*NV*HH + n*HH + h)*WW + w)*2;
        float gx = gp[0], gy = gp[1];
        float ix = ((gx + 1.f)*WW - 1.f) * 0.5f;
        float iy = ((gy + 1.f)*HH - 1.f) * 0.5f;
        float x0f = floorf(ix), y0f = floorf(iy);
        float fx = ix - x0f, fy = iy - y0f;
        int x0 = (int)x0f, y0 = (int)y0f;
        int xc0 = min(max(x0, 0), WW-1), xc1 = min(max(x0+1, 0), WW-1);
        int yc0 = min(max(y0, 0), HH-1), yc1 = min(max(y0+1, 0), HH-1);
        float w00 = (1.f-fx)*(1.f-fy), w01 = fx*(1.f-fy);
        float w10 = (1.f-fx)*fy,       w11 = fx*fy;
        const float4* s00 = (const float4*)(g_s + ((size_t)b*HWP + yc0*WW + xc0)*DD);
        const float4* s01 = (const float4*)(g_s + ((size_t)b*HWP + yc0*WW + xc1)*DD);
        const float4* s10 = (const float4*)(g_s + ((size_t)b*HWP + yc1*WW + xc0)*DD);
        const float4* s11 = (const float4*)(g_s + ((size_t)b*HWP + yc1*WW + xc1)*DD);
        const float* wb = weight + ((size_t)b*DD*NV + n)*HWP + hw;
        #pragma unroll
        for (int q = 0; q < 4; q++) {
            float4 a00 = __ldg(s00 + q), a01 = __ldg(s01 + q);
            float4 a10 = __ldg(s10 + q), a11 = __ldg(s11 + q);
            float bx = w00*a00.x + w01*a01.x + w10*a10.x + w11*a11.x;
            float by = w00*a00.y + w01*a01.y + w10*a10.y + w11*a11.y;
            float bz = w00*a00.z + w01*a01.z + w10*a10.z + w11*a11.z;
            float bw = w00*a00.w + w01*a01.w + w10*a10.w + w11*a11.w;
            agg[q*4+0] += __ldg(wb + (size_t)(q*4+0)*NV*HWP) * bx;
            agg[q*4+1] += __ldg(wb + (size_t)(q*4+1)*NV*HWP) * by;
            agg[q*4+2] += __ldg(wb + (size_t)(q*4+2)*NV*HWP) * bz;
            agg[q*4+3] += __ldg(wb + (size_t)(q*4+3)*NV*HWP) * bw;
        }
    }

    float m = agg[0];
    #pragma unroll
    for (int d = 1; d < DD; d++) m = fmaxf(m, agg[d]);
    float e[DD]; float sum = 0.f;
    #pragma unroll
    for (int d = 0; d < DD; d++) { e[d] = expf(agg[d] - m); sum += e[d]; }
    float rs = 1.f / sum;

    const float* dsB = depth_sample + (size_t)b*DD*HWP + hw;
    float dep;
    if (*is_inverse) {
        float di = 0.f;
        #pragma unroll
        for (int d = 0; d < DD; d++) {
            float sc = e[d] * rs;
            out_score[((size_t)b*DD + d)*HWP + hw] = sc;
            di += (float)d * sc;
        }
        float invmin = 1.f / dsB[(size_t)(DD-1)*HWP];
        float invmax = 1.f / dsB[0];
        dep = 1.f / (invmax + di * (1.f/(float)(DD-1)) * (invmin - invmax));
    } else {
        dep = 0.f;
        #pragma unroll
        for (int d = 0; d < DD; d++) {
            float sc = e[d] * rs;
            out_score[((size_t)b*DD + d)*HWP + hw] = sc;
            dep += dsB[(size_t)d*HWP] * sc;
        }
    }
    out_depth[p] = dep;
}

// ---------------- launch ----------------
extern "C" void kernel_launch(void* const* d_in, const int* in_sizes, int n_in,
                              void* d_out, int out_size) {
    const float* ref_feature  = (const float*)d_in[0];
    const float* src_features = (const float*)d_in[1];
    const float* ref_proj     = (const float*)d_in[2];
    const float* src_projs    = (const float*)d_in[3];
    const float* depth_sample = (const float*)d_in[4];
    const float* grid         = (const float*)d_in[5];
    const float* weight       = (const float*)d_in[6];
    const float* pw_w0  = (const float*)d_in[7];
    const float* pw_g0  = (const float*)d_in[8];
    const float* pw_b0  = (const float*)d_in[9];
    const float* pw_w1  = (const float*)d_in[10];
    const float* pw_g1  = (const float*)d_in[11];
    const float* pw_b1  = (const float*)d_in[12];
    const float* pw_w2  = (const float*)d_in[13];
    const float* pw_c2b = (const float*)d_in[14];
    const float* sn_w0  = (const float*)d_in[15];
    const float* sn_g0  = (const float*)d_in[16];
    const float* sn_b0  = (const float*)d_in[17];
    const float* sn_w1  = (const float*)d_in[18];
    const float* sn_g1  = (const float*)d_in[19];
    const float* sn_b1  = (const float*)d_in[20];
    const float* sn_w2  = (const float*)d_in[21];
    const float* sn_c2b = (const float*)d_in[22];
    const int*   is_inv = (const int*)d_in[23];

    float* out       = (float*)d_out;
    float* out_depth = out;                         // B*H*W
    float* out_score = out + (size_t)BB*HWP;        // B*D*H*W
    float* out_vw    = out + (size_t)BB*HWP + (size_t)BB*DD*HWP; // B*V*H*W

    k_transpose<<<dim3(HWP/64, VV*BB + BB), 256>>>(ref_feature, src_features);
    k_proj<<<1, 32>>>(ref_proj, src_projs);
    k_main<<<BB*HWP/8, 128>>>(depth_sample,
                              pw_w0, pw_g0, pw_b0, pw_w1, pw_g1, pw_b1, pw_w2, pw_c2b,
                              sn_w0, sn_g0, sn_b0, sn_w1, sn_g1, sn_b1, sn_w2, sn_c2b,
                              out_vw);
    k_final<<<(BB*HWP + 127)/128, 128>>>(grid, weight, depth_sample, is_inv,
                                         out_depth, out_score);
}

// round 2
// speedup vs baseline: 1.1101x; 1.1101x over previous
#include <cuda_runtime.h>
#include <cuda_fp16.h>
#include <math.h>

#define BB 2
#define CC 64
#define HH 128
#define WW 160
#define DD 16
#define VV 4
#define NV 9
#define HWP (HH*WW)

// ---------------- scratch (static device memory; no allocation) ----------------
__device__ __align__(16) __half g_srcT[(size_t)VV*BB*HWP*CC]; // fp16 [v*B+b][hw][c]
__device__ __align__(16) float  g_refT[(size_t)BB*HWP*CC];    // fp32 [b][hw][c]
__device__ float g_proj[VV*BB*12];
__device__ __align__(16) float g_s[(size_t)BB*HWP*DD];        // s channels-last [b][hw][d]

#define BNS 0.9999950000374997f

// ---------------- K0: transpose [C,HW] -> [HW,C]; src -> fp16, ref -> fp32 ----------------
__global__ void k_transpose(const float* __restrict__ ref, const float* __restrict__ src) {
    __shared__ float tile[64][65];
    int img = blockIdx.y;          // 0..7 = src v*B+b, 8..9 = ref b
    int hw0 = blockIdx.x * 64;
    const float* in = (img < VV*BB) ? (src + (size_t)img*CC*HWP)
                                    : (ref + (size_t)(img - VV*BB)*CC*HWP);
    for (int k = threadIdx.x; k < 64*64; k += blockDim.x) {
        int c = k >> 6, hwl = k & 63;
        tile[hwl][c] = in[(size_t)c*HWP + hw0 + hwl];
    }
    __syncthreads();
    if (img < VV*BB) {
        __half* out = g_srcT + (size_t)img*HWP*CC;
        for (int k = threadIdx.x; k < 64*64; k += blockDim.x) {
            int hwl = k >> 6, c = k & 63;
            out[(size_t)(hw0+hwl)*CC + c] = __float2half_rn(tile[hwl][c]);
        }
    } else {
        float* out = g_refT + (size_t)(img - VV*BB)*HWP*CC;
        for (int k = threadIdx.x; k < 64*64; k += blockDim.x) {
            int hwl = k >> 6, c = k & 63;
            out[(size_t)(hw0+hwl)*CC + c] = tile[hwl][c];
        }
    }
}

// ---------------- K1: proj = src_proj @ inv(ref_proj) ----------------
__global__ void k_proj(const float* __restrict__ ref_proj, const float* __restrict__ src_projs) {
    int t = threadIdx.x;
    if (t >= VV*BB) return;
    int v = t / BB, b = t % BB;
    float a[4][4], inv[4][4];
    #pragma unroll
    for (int i = 0; i < 4; i++)
        #pragma unroll
        for (int j = 0; j < 4; j++) {
            a[i][j] = ref_proj[b*16 + i*4 + j];
            inv[i][j] = (i == j) ? 1.f : 0.f;
        }
    for (int col = 0; col < 4; col++) {
        int piv = col; float best = fabsf(a[col][col]);
        for (int r = col+1; r < 4; r++) { float av = fabsf(a[r][col]); if (av > best) { best = av; piv = r; } }
        if (piv != col) {
            for (int j = 0; j < 4; j++) {
                float tm = a[col][j]; a[col][j] = a[piv][j]; a[piv][j] = tm;
                tm = inv[col][j]; inv[col][j] = inv[piv][j]; inv[piv][j] = tm;
            }
        }
        float dsc = 1.f / a[col][col];
        for (int j = 0; j < 4; j++) { a[col][j] *= dsc; inv[col][j] *= dsc; }
        for (int r = 0; r < 4; r++) {
            if (r == col) continue;
            float f = a[r][col];
            for (int j = 0; j < 4; j++) { a[r][j] -= f*a[col][j]; inv[r][j] -= f*inv[col][j]; }
        }
    }
    const float* s = src_projs + (size_t)(v*BB + b)*16;
    float* o = g_proj + (v*BB + b)*12;
    for (int i = 0; i < 3; i++)
        for (int j = 0; j < 4; j++) {
            float acc = 0.f;
            for (int k = 0; k < 4; k++) acc += s[i*4 + k] * inv[k][j];
            o[i*4 + j] = acc;
        }
}

// ---------------- small MLP (8 -> 16 -> 8 -> 1), weights in shared ----------------
__device__ __forceinline__ float mlp8(const float* __restrict__ sw, const float in8[8]) {
    float h1[16];
    #pragma unroll
    for (int j = 0; j < 16; j++) {
        float a = 0.f;
        #pragma unroll
        for (int g = 0; g < 8; g++) a += sw[j*8 + g] * in8[g];
        h1[j] = fmaxf(0.f, a * sw[128 + j] + sw[144 + j]);
    }
    float o = sw[312];
    #pragma unroll
    for (int k = 0; k < 8; k++) {
        float a = 0.f;
        #pragma unroll
        for (int j = 0; j < 16; j++) a += sw[160 + k*16 + j] * h1[j];
        float h2 = fmaxf(0.f, a * sw[288 + k] + sw[296 + k]);
        o += sw[304 + k] * h2;
    }
    return o;
}

// ---------------- K2: warp + group correlation + pixelwise net + similarity net ----------------
__global__ void __launch_bounds__(128)
k_main(const float* __restrict__ depth_sample,
       const float* __restrict__ pw_w0, const float* __restrict__ pw_g0, const float* __restrict__ pw_b0,
       const float* __restrict__ pw_w1, const float* __restrict__ pw_g1, const float* __restrict__ pw_b1,
       const float* __restrict__ pw_w2, const float* __restrict__ pw_c2b,
       const float* __restrict__ sn_w0, const float* __restrict__ sn_g0, const float* __restrict__ sn_b0,
       const float* __restrict__ sn_w1, const float* __restrict__ sn_g1, const float* __restrict__ sn_b1,
       const float* __restrict__ sn_w2, const float* __restrict__ sn_c2b,
       float* __restrict__ out_vw) {
    __shared__ float sw[2][320];
    __shared__ float simv[8][16][8];
    __shared__ float simsum[8][16][8];
    __shared__ float wsum[8];

    int tid = threadIdx.x;
    {
        int i = tid;
        sw[0][i] = pw_w0[i];       sw[1][i] = sn_w0[i];
        sw[0][160 + i] = pw_w1[i]; sw[1][160 + i] = sn_w1[i];
    }
    if (tid < 16) {
        sw[0][128 + tid] = pw_g0[tid] * BNS; sw[0][144 + tid] = pw_b0[tid];
        sw[1][128 + tid] = sn_g0[tid] * BNS; sw[1][144 + tid] = sn_b0[tid];
    }
    if (tid < 8) {
        sw[0][288 + tid] = pw_g1[tid] * BNS; sw[0][296 + tid] = pw_b1[tid]; sw[0][304 + tid] = pw_w2[tid];
        sw[1][288 + tid] = sn_g1[tid] * BNS; sw[1][296 + tid] = sn_b1[tid]; sw[1][304 + tid] = sn_w2[tid];
    }
    if (tid == 0) { sw[0][312] = pw_c2b[0]; sw[1][312] = sn_c2b[0]; }
    __syncthreads();

    int pix  = tid >> 4;
    int lane = tid & 15;
    int p = blockIdx.x * 8 + pix;
    int b  = p / HWP;
    int hw = p - b * HWP;
    int h = hw / WW, w = hw - h * WW;
    float wf = (float)w, hf = (float)h;

    const float4 rf = *(const float4*)(g_refT + (size_t)p*CC + lane*4);

    #pragma unroll
    for (int g = 0; g < 8; g++) simsum[pix][lane][g] = 0.f;
    if (lane == 0) wsum[pix] = 0.f;
    __syncwarp();

    const float* dsB = depth_sample + (size_t)b*DD*HWP + hw;

    for (int v = 0; v < VV; v++) {
        const float* M = g_proj + (v*BB + b)*12;
        float rx = M[0]*wf + M[1]*hf + M[2];
        float ry = M[4]*wf + M[5]*hf + M[6];
        float rz = M[8]*wf + M[9]*hf + M[10];
        float t0 = M[3], t1 = M[7], t2 = M[11];
        const __half* srcB = g_srcT + (size_t)(v*BB + b)*HWP*CC;

        #pragma unroll 2
        for (int d = 0; d < DD; d++) {
            float dep = __ldg(dsB + (size_t)d*HWP);
            float px = rx*dep + t0, py = ry*dep + t1, pz = rz*dep + t2;
            if (pz <= 0.001f) { px = (float)WW; py = (float)HH; pz = 1.f; }
            float rinv = 1.f / pz;
            float ix = px * rinv, iy = py * rinv;
            float x0f = floorf(ix), y0f = floorf(iy);
            float fx = ix - x0f, fy = iy - y0f;
            int x0 = (int)x0f, y0 = (int)y0f;
            int x1 = x0 + 1, y1 = y0 + 1;
            bool vx0 = (x0 >= 0) & (x0 < WW);
            bool vx1 = (x1 >= 0) & (x1 < WW);
            bool vy0 = (y0 >= 0) & (y0 < HH);
            bool vy1 = (y1 >= 0) & (y1 < HH);
            float w00 = (1.f-fx)*(1.f-fy) * (float)(vx0 && vy0);
            float w01 = fx*(1.f-fy)       * (float)(vx1 && vy0);
            float w10 = (1.f-fx)*fy       * (float)(vx0 && vy1);
            float w11 = fx*fy             * (float)(vx1 && vy1);
            int xc0 = min(max(x0, 0), WW-1), xc1 = min(max(x1, 0), WW-1);
            int yc0 = min(max(y0, 0), HH-1), yc1 = min(max(y1, 0), HH-1);
            const uint2* p00 = (const uint2*)(srcB + (size_t)(yc0*WW + xc0)*CC) + lane;
            const uint2* p01 = (const uint2*)(srcB + (size_t)(yc0*WW + xc1)*CC) + lane;
            const uint2* p10 = (const uint2*)(srcB + (size_t)(yc1*WW + xc0)*CC) + lane;
            const uint2* p11 = (const uint2*)(srcB + (size_t)(yc1*WW + xc1)*CC) + lane;
            uint2 u00 = __ldg(p00), u01 = __ldg(p01), u10 = __ldg(p10), u11 = __ldg(p11);
            float2 a00 = __half22float2(*(const __half2*)&u00.x);
            float2 b00 = __half22float2(*(const __half2*)&u00.y);
            float2 a01 = __half22float2(*(const __half2*)&u01.x);
            float2 b01 = __half22float2(*(const __half2*)&u01.y);
            float2 a10 = __half22float2(*(const __half2*)&u10.x);
            float2 b10 = __half22float2(*(const __half2*)&u10.y);
            float2 a11 = __half22float2(*(const __half2*)&u11.x);
            float2 b11 = __half22float2(*(const __half2*)&u11.y);
            float cx = w00*a00.x + w01*a01.x + w10*a10.x + w11*a11.x;
            float cy = w00*a00.y + w01*a01.y + w10*a10.y + w11*a11.y;
            float cz = w00*b00.x + w01*b01.x + w10*b10.x + w11*b11.x;
            float cw = w00*b00.y + w01*b01.y + w10*b10.y + w11*b11.y;
            float part = cx*rf.x + cy*rf.y + cz*rf.z + cw*rf.w;
            part += __shfl_xor_sync(0xffffffffu, part, 1);
            if (!(lane & 1)) simv[pix][d][lane >> 1] = part * 0.125f;
        }
        __syncwarp();

        float in8[8];
        #pragma unroll
        for (int g = 0; g < 8; g++) in8[g] = simv[pix][lane][g];
        float o = mlp8(sw[0], in8);
        float vwv = 1.f / (1.f + expf(-o));
        #pragma unroll
        for (int k = 8; k >= 1; k >>= 1)
            vwv = fmaxf(vwv, __shfl_xor_sync(0xffffffffu, vwv, k, 16));
        #pragma unroll
        for (int g = 0; g < 8; g++) simsum[pix][lane][g] += in8[g] * vwv;
        if (lane == 0) {
            wsum[pix] += vwv;
            out_vw[((size_t)b*VV + v)*HWP + hw] = vwv;
        }
        __syncwarp();
    }

    float rws = 1.f / wsum[pix];
    float in8[8];
    #pragma unroll
    for (int g = 0; g < 8; g++) in8[g] = simsum[pix][lane][g] * rws;
    float sval = mlp8(sw[1], in8);
    g_s[(size_t)p*DD + lane] = sval;
}

// ---------------- K3: grid-sample + NN aggregation + softmax + depth ----------------
// 4 threads per pixel; thread q owns depths [4q, 4q+4)
__global__ void __launch_bounds__(128)
k_final(const float* __restrict__ grid, const float* __restrict__ weight,
        const float* __restrict__ depth_sample, const int* __restrict__ is_inverse,
        float* __restrict__ out_depth, float* __restrict__ out_score) {
    int t = blockIdx.x * blockDim.x + threadIdx.x;
    int p = t >> 2;
    int q = t & 3;
    if (p >= BB*HWP) return;
    int b  = p / HWP;
    int hw = p - b * HWP;
    int h = hw / WW, w = hw - h * WW;

    float agg[4] = {0.f, 0.f, 0.f, 0.f};

    const float* wbase = weight + ((size_t)b*DD*NV)*HWP + hw + (size_t)(q*4)*NV*HWP;
    #pragma unroll
    for (int n = 0; n < NV; n++) {
        const float* gp = grid + (((size_t)b*NV*HH + n*HH + h)*WW + w)*2;
        float gx = __ldg(gp), gy = __ldg(gp + 1);
        float ix = ((gx + 1.f)*WW - 1.f) * 0.5f;
        float iy = ((gy + 1.f)*HH - 1.f) * 0.5f;
        float x0f = floorf(ix), y0f = floorf(iy);
        float fx = ix - x0f, fy = iy - y0f;
        int x0 = (int)x0f, y0 = (int)y0f;
        int xc0 = min(max(x0, 0), WW-1), xc1 = min(max(x0+1, 0), WW-1);
        int yc0 = min(max(y0, 0), HH-1), yc1 = min(max(y0+1, 0), HH-1);
        float w00 = (1.f-fx)*(1.f-fy), w01 = fx*(1.f-fy);
        float w10 = (1.f-fx)*fy,       w11 = fx*fy;
        float4 a00 = __ldg((const float4*)(g_s + ((size_t)b*HWP + yc0*WW + xc0)*DD) + q);
        float4 a01 = __ldg((const float4*)(g_s + ((size_t)b*HWP + yc0*WW + xc1)*DD) + q);
        float4 a10 = __ldg((const float4*)(g_s + ((size_t)b*HWP + yc1*WW + xc0)*DD) + q);
        float4 a11 = __ldg((const float4*)(g_s + ((size_t)b*HWP + yc1*WW + xc1)*DD) + q);
        float bx = w00*a00.x + w01*a01.x + w10*a10.x + w11*a11.x;
        float by = w00*a00.y + w01*a01.y + w10*a10.y + w11*a11.y;
        float bz = w00*a00.z + w01*a01.z + w10*a10.z + w11*a11.z;
        float bw = w00*a00.w + w01*a01.w + w10*a10.w + w11*a11.w;
        const float* wb = wbase + (size_t)n*HWP;
        agg[0] += __ldg(wb)                      * bx;
        agg[1] += __ldg(wb + (size_t)1*NV*HWP)   * by;
        agg[2] += __ldg(wb + (size_t)2*NV*HWP)   * bz;
        agg[3] += __ldg(wb + (size_t)3*NV*HWP)   * bw;
    }

    // softmax over 16 depths spread across 4 threads (width-4 shuffle group)
    float m = fmaxf(fmaxf(agg[0], agg[1]), fmaxf(agg[2], agg[3]));
    m = fmaxf(m, __shfl_xor_sync(0xffffffffu, m, 1, 4));
    m = fmaxf(m, __shfl_xor_sync(0xffffffffu, m, 2, 4));
    float e[4]; float sum = 0.f;
    #pragma unroll
    for (int j = 0; j < 4; j++) { e[j] = expf(agg[j] - m); sum += e[j]; }
    sum += __shfl_xor_sync(0xffffffffu, sum, 1, 4);
    sum += __shfl_xor_sync(0xffffffffu, sum, 2, 4);
    float rs = 1.f / sum;

    const float* dsB = depth_sample + (size_t)b*DD*HWP + hw;
    float dep = 0.f;
    int inv = *is_inverse;
    #pragma unroll
    for (int j = 0; j < 4; j++) {
        float sc = e[j] * rs;
        int d = q*4 + j;
        out_score[((size_t)b*DD + d)*HWP + hw] = sc;
        if (inv) dep += (float)d * sc;
        else     dep += __ldg(dsB + (size_t)d*HWP) * sc;
    }
    dep += __shfl_xor_sync(0xffffffffu, dep, 1, 4);
    dep += __shfl_xor_sync(0xffffffffu, dep, 2, 4);
    if (q == 0) {
        if (inv) {
            float invmin = 1.f / __ldg(dsB + (size_t)(DD-1)*HWP);
            float invmax = 1.f / __ldg(dsB);
            dep = 1.f / (invmax + dep * (1.f/(float)(DD-1)) * (invmin - invmax));
        }
        out_depth[p] = dep;
    }
}

// ---------------- launch ----------------
extern "C" void kernel_launch(void* const* d_in, const int* in_sizes, int n_in,
                              void* d_out, int out_size) {
    const float* ref_feature  = (const float*)d_in[0];
    const float* src_features = (const float*)d_in[1];
    const float* ref_proj     = (const float*)d_in[2];
    const float* src_projs    = (const float*)d_in[3];
    const float* depth_sample = (const float*)d_in[4];
    const float* grid         = (const float*)d_in[5];
    const float* weight       = (const float*)d_in[6];
    const float* pw_w0  = (const float*)d_in[7];
    const float* pw_g0  = (const float*)d_in[8];
    const float* pw_b0  = (const float*)d_in[9];
    const float* pw_w1  = (const float*)d_in[10];
    const float* pw_g1  = (const float*)d_in[11];
    const float* pw_b1  = (const float*)d_in[12];
    const float* pw_w2  = (const float*)d_in[13];
    const float* pw_c2b = (const float*)d_in[14];
    const float* sn_w0  = (const float*)d_in[15];
    const float* sn_g0  = (const float*)d_in[16];
    const float* sn_b0  = (const float*)d_in[17];
    const float* sn_w1  = (const float*)d_in[18];
    const float* sn_g1  = (const float*)d_in[19];
    const float* sn_b1  = (const float*)d_in[20];
    const float* sn_w2  = (const float*)d_in[21];
    const float* sn_c2b = (const float*)d_in[22];
    const int*   is_inv = (const int*)d_in[23];

    float* out       = (float*)d_out;
    float* out_depth = out;
    float* out_score = out + (size_t)BB*HWP;
    float* out_vw    = out + (size_t)BB*HWP + (size_t)BB*DD*HWP;

    k_transpose<<<dim3(HWP/64, VV*BB + BB), 256>>>(ref_feature, src_features);
    k_proj<<<1, 32>>>(ref_proj, src_projs);
    k_main<<<BB*HWP/8, 128>>>(depth_sample,
                              pw_w0, pw_g0, pw_b0, pw_w1, pw_g1, pw_b1, pw_w2, pw_c2b,
                              sn_w0, sn_g0, sn_b0, sn_w1, sn_g1, sn_b1, sn_w2, sn_c2b,
                              out_vw);
    k_final<<<(BB*HWP*4 + 127)/128, 128>>>(grid, weight, depth_sample, is_inv,
                                           out_depth, out_score);
}

// round 3
// speedup vs baseline: 1.2719x; 1.1458x over previous
#include <cuda_runtime.h>
#include <cuda_fp16.h>
#include <math.h>
#include <stdint.h>

#define BB 2
#define CC 64
#define HH 128
#define WW 160
#define DD 16
#define VV 4
#define NV 9
#define HWP (HH*WW)

// ---------------- scratch (static device memory; no allocation) ----------------
__device__ __align__(16) __half g_srcT[(size_t)VV*BB*HWP*CC]; // fp16 [v*B+b][hw][c]
__device__ __align__(16) float  g_refT[(size_t)BB*HWP*CC];    // fp32 [b][hw][c]
__device__ float g_proj[VV*BB*12];
__device__ __align__(16) float g_s[(size_t)BB*HWP*DD];        // s channels-last [b][hw][d]

#define BNS 0.9999950000374997f

// ---------------- K0: transpose [C,HW] -> [HW,C]; src -> fp16, ref -> fp32 ----------------
__global__ void k_transpose(const float* __restrict__ ref, const float* __restrict__ src) {
    __shared__ float tile[64][65];
    int img = blockIdx.y;          // 0..7 = src v*B+b, 8..9 = ref b
    int hw0 = blockIdx.x * 64;
    const float* in = (img < VV*BB) ? (src + (size_t)img*CC*HWP)
                                    : (ref + (size_t)(img - VV*BB)*CC*HWP);
    for (int k = threadIdx.x; k < 64*64; k += blockDim.x) {
        int c = k >> 6, hwl = k & 63;
        tile[hwl][c] = in[(size_t)c*HWP + hw0 + hwl];
    }
    __syncthreads();
    if (img < VV*BB) {
        __half* out = g_srcT + (size_t)img*HWP*CC;
        for (int k = threadIdx.x; k < 64*64; k += blockDim.x) {
            int hwl = k >> 6, c = k & 63;
            out[(size_t)(hw0+hwl)*CC + c] = __float2half_rn(tile[hwl][c]);
        }
    } else {
        float* out = g_refT + (size_t)(img - VV*BB)*HWP*CC;
        for (int k = threadIdx.x; k < 64*64; k += blockDim.x) {
            int hwl = k >> 6, c = k & 63;
            out[(size_t)(hw0+hwl)*CC + c] = tile[hwl][c];
        }
    }
}

// ---------------- K1: proj = src_proj @ inv(ref_proj) ----------------
__global__ void k_proj(const float* __restrict__ ref_proj, const float* __restrict__ src_projs) {
    int t = threadIdx.x;
    if (t >= VV*BB) return;
    int v = t / BB, b = t % BB;
    float a[4][4], inv[4][4];
    #pragma unroll
    for (int i = 0; i < 4; i++)
        #pragma unroll
        for (int j = 0; j < 4; j++) {
            a[i][j] = ref_proj[b*16 + i*4 + j];
            inv[i][j] = (i == j) ? 1.f : 0.f;
        }
    for (int col = 0; col < 4; col++) {
        int piv = col; float best = fabsf(a[col][col]);
        for (int r = col+1; r < 4; r++) { float av = fabsf(a[r][col]); if (av > best) { best = av; piv = r; } }
        if (piv != col) {
            for (int j = 0; j < 4; j++) {
                float tm = a[col][j]; a[col][j] = a[piv][j]; a[piv][j] = tm;
                tm = inv[col][j]; inv[col][j] = inv[piv][j]; inv[piv][j] = tm;
            }
        }
        float dsc = 1.f / a[col][col];
        for (int j = 0; j < 4; j++) { a[col][j] *= dsc; inv[col][j] *= dsc; }
        for (int r = 0; r < 4; r++) {
            if (r == col) continue;
            float f = a[r][col];
            for (int j = 0; j < 4; j++) { a[r][j] -= f*a[col][j]; inv[r][j] -= f*inv[col][j]; }
        }
    }
    const float* s = src_projs + (size_t)(v*BB + b)*16;
    float* o = g_proj + (v*BB + b)*12;
    for (int i = 0; i < 3; i++)
        for (int j = 0; j < 4; j++) {
            float acc = 0.f;
            for (int k = 0; k < 4; k++) acc += s[i*4 + k] * inv[k][j];
            o[i*4 + j] = acc;
        }
}

// ---------------- small MLP (8 -> 16 -> 8 -> 1), float4 shared loads ----------------
// layout (floats): [0:128) w0 (16x8), [128:144) gs0, [144:160) b0, [160:288) w1 (8x16),
//                  [288:296) gs1, [296:304) b1, [304:312) w2, [312] c2b
__device__ __forceinline__ float mlp8(const float* __restrict__ sw, const float in8[8]) {
    float h1[16];
    #pragma unroll
    for (int j = 0; j < 16; j++) {
        float4 wa = *(const float4*)&sw[j*8];
        float4 wb = *(const float4*)&sw[j*8 + 4];
        float a = wa.x*in8[0] + wa.y*in8[1] + wa.z*in8[2] + wa.w*in8[3]
                + wb.x*in8[4] + wb.y*in8[5] + wb.z*in8[6] + wb.w*in8[7];
        h1[j] = fmaxf(0.f, a * sw[128 + j] + sw[144 + j]);
    }
    float o = sw[312];
    #pragma unroll
    for (int k = 0; k < 8; k++) {
        float a = 0.f;
        #pragma unroll
        for (int q = 0; q < 4; q++) {
            float4 wv = *(const float4*)&sw[160 + k*16 + q*4];
            a += wv.x*h1[q*4+0] + wv.y*h1[q*4+1] + wv.z*h1[q*4+2] + wv.w*h1[q*4+3];
        }
        float h2 = fmaxf(0.f, a * sw[288 + k] + sw[296 + k]);
        o += sw[304 + k] * h2;
    }
    return o;
}

// ---------------- K2: warp + group correlation + pixelwise net + similarity net ----------------
// block = 128 threads = 8 pixels, 16 lanes per pixel.
// Phase A: lane d computes coords for depth d.  Phase B: lane = channel quad.
__global__ void __launch_bounds__(128)
k_main(const float* __restrict__ depth_sample,
       const float* __restrict__ pw_w0, const float* __restrict__ pw_g0, const float* __restrict__ pw_b0,
       const float* __restrict__ pw_w1, const float* __restrict__ pw_g1, const float* __restrict__ pw_b1,
       const float* __restrict__ pw_w2, const float* __restrict__ pw_c2b,
       const float* __restrict__ sn_w0, const float* __restrict__ sn_g0, const float* __restrict__ sn_b0,
       const float* __restrict__ sn_w1, const float* __restrict__ sn_g1, const float* __restrict__ sn_b1,
       const float* __restrict__ sn_w2, const float* __restrict__ sn_c2b,
       float* __restrict__ out_vw) {
    __shared__ float sw[2][320];
    __shared__ __align__(16) uint32_t scoord[8][16][8]; // [pix][d][idx00..11, w00..11(half2dup)]
    __shared__ float simv[8][16][8];
    __shared__ float simsum[8][16][8];
    __shared__ float wsum[8];

    int tid = threadIdx.x;
    {
        int i = tid;
        sw[0][i] = pw_w0[i];       sw[1][i] = sn_w0[i];
        sw[0][160 + i] = pw_w1[i]; sw[1][160 + i] = sn_w1[i];
    }
    if (tid < 16) {
        sw[0][128 + tid] = pw_g0[tid] * BNS; sw[0][144 + tid] = pw_b0[tid];
        sw[1][128 + tid] = sn_g0[tid] * BNS; sw[1][144 + tid] = sn_b0[tid];
    }
    if (tid < 8) {
        sw[0][288 + tid] = pw_g1[tid] * BNS; sw[0][296 + tid] = pw_b1[tid]; sw[0][304 + tid] = pw_w2[tid];
        sw[1][288 + tid] = sn_g1[tid] * BNS; sw[1][296 + tid] = sn_b1[tid]; sw[1][304 + tid] = sn_w2[tid];
    }
    if (tid == 0) { sw[0][312] = pw_c2b[0]; sw[1][312] = sn_c2b[0]; }
    __syncthreads();

    int pix  = tid >> 4;
    int lane = tid & 15;
    int p = blockIdx.x * 8 + pix;
    int b  = p / HWP;
    int hw = p - b * HWP;
    int h = hw / WW, w = hw - h * WW;
    float wf = (float)w, hf = (float)h;

    const float4 rf = *(const float4*)(g_refT + (size_t)p*CC + lane*4);

    // depth for the depth-index this lane owns (view-invariant)
    float myDep = __ldg(depth_sample + (size_t)b*DD*HWP + (size_t)lane*HWP + hw);

    #pragma unroll
    for (int g = 0; g < 8; g++) simsum[pix][lane][g] = 0.f;
    if (lane == 0) wsum[pix] = 0.f;
    __syncwarp();

    for (int v = 0; v < VV; v++) {
        const float* M = g_proj + (v*BB + b)*12;
        float rx = M[0]*wf + M[1]*hf + M[2];
        float ry = M[4]*wf + M[5]*hf + M[6];
        float rz = M[8]*wf + M[9]*hf + M[10];
        float t0 = M[3], t1 = M[7], t2 = M[11];
        const __half* srcB = g_srcT + (size_t)(v*BB + b)*HWP*CC;

        // ---- Phase A: this lane computes coords for depth d = lane ----
        {
            float px = rx*myDep + t0, py = ry*myDep + t1, pz = rz*myDep + t2;
            if (pz <= 0.001f) { px = (float)WW; py = (float)HH; pz = 1.f; }
            float ix = __fdividef(px, pz);
            float iy = __fdividef(py, pz);
            float x0f = floorf(ix), y0f = floorf(iy);
            float fx = ix - x0f, fy = iy - y0f;
            int x0 = (int)x0f, y0 = (int)y0f;
            int x1 = x0 + 1, y1 = y0 + 1;
            bool vx0 = (x0 >= 0) & (x0 < WW);
            bool vx1 = (x1 >= 0) & (x1 < WW);
            bool vy0 = (y0 >= 0) & (y0 < HH);
            bool vy1 = (y1 >= 0) & (y1 < HH);
            float w00 = (1.f-fx)*(1.f-fy) * (float)(vx0 && vy0);
            float w01 = fx*(1.f-fy)       * (float)(vx1 && vy0);
            float w10 = (1.f-fx)*fy       * (float)(vx0 && vy1);
            float w11 = fx*fy             * (float)(vx1 && vy1);
            int xc0 = min(max(x0, 0), WW-1), xc1 = min(max(x1, 0), WW-1);
            int yc0 = min(max(y0, 0), HH-1), yc1 = min(max(y1, 0), HH-1);
            int r0 = yc0*WW, r1 = yc1*WW;
            uint32_t* sc = scoord[pix][lane];
            sc[0] = (uint32_t)(r0 + xc0);
            sc[1] = (uint32_t)(r0 + xc1);
            sc[2] = (uint32_t)(r1 + xc0);
            sc[3] = (uint32_t)(r1 + xc1);
            __half2 h00 = __float2half2_rn(w00);
            __half2 h01 = __float2half2_rn(w01);
            __half2 h10 = __float2half2_rn(w10);
            __half2 h11 = __float2half2_rn(w11);
            sc[4] = *reinterpret_cast<uint32_t*>(&h00);
            sc[5] = *reinterpret_cast<uint32_t*>(&h01);
            sc[6] = *reinterpret_cast<uint32_t*>(&h10);
            sc[7] = *reinterpret_cast<uint32_t*>(&h11);
        }
        __syncwarp();

        // ---- Phase B: sample all 16 depths; this lane = channel quad ----
        #pragma unroll
        for (int d = 0; d < DD; d++) {
            uint4 ci = *(const uint4*)&scoord[pix][d][0];
            uint4 cw = *(const uint4*)&scoord[pix][d][4];
            uint2 u00 = __ldg((const uint2*)(srcB + (size_t)ci.x*CC) + lane);
            uint2 u01 = __ldg((const uint2*)(srcB + (size_t)ci.y*CC) + lane);
            uint2 u10 = __ldg((const uint2*)(srcB + (size_t)ci.z*CC) + lane);
            uint2 u11 = __ldg((const uint2*)(srcB + (size_t)ci.w*CC) + lane);
            __half2 w00 = *reinterpret_cast<const __half2*>(&cw.x);
            __half2 w01 = *reinterpret_cast<const __half2*>(&cw.y);
            __half2 w10 = *reinterpret_cast<const __half2*>(&cw.z);
            __half2 w11 = *reinterpret_cast<const __half2*>(&cw.w);
            __half2 m0 = __hmul2(*reinterpret_cast<const __half2*>(&u00.x), w00);
            __half2 m1 = __hmul2(*reinterpret_cast<const __half2*>(&u00.y), w00);
            m0 = __hfma2(*reinterpret_cast<const __half2*>(&u01.x), w01, m0);
            m1 = __hfma2(*reinterpret_cast<const __half2*>(&u01.y), w01, m1);
            m0 = __hfma2(*reinterpret_cast<const __half2*>(&u10.x), w10, m0);
            m1 = __hfma2(*reinterpret_cast<const __half2*>(&u10.y), w10, m1);
            m0 = __hfma2(*reinterpret_cast<const __half2*>(&u11.x), w11, m0);
            m1 = __hfma2(*reinterpret_cast<const __half2*>(&u11.y), w11, m1);
            float2 f0 = __half22float2(m0);
            float2 f1 = __half22float2(m1);
            float part = f0.x*rf.x + f0.y*rf.y + f1.x*rf.z + f1.y*rf.w;
            part += __shfl_xor_sync(0xffffffffu, part, 1);
            if (!(lane & 1)) simv[pix][d][lane >> 1] = part * 0.125f;
        }
        __syncwarp();

        // ---- pixelwise net: lane owns depth d = lane ----
        float in8[8];
        #pragma unroll
        for (int g = 0; g < 8; g++) in8[g] = simv[pix][lane][g];
        float o = mlp8(sw[0], in8);
        float vwv = 1.f / (1.f + expf(-o));
        #pragma unroll
        for (int k = 8; k >= 1; k >>= 1)
            vwv = fmaxf(vwv, __shfl_xor_sync(0xffffffffu, vwv, k, 16));
        #pragma unroll
        for (int g = 0; g < 8; g++) simsum[pix][lane][g] += in8[g] * vwv;
        if (lane == 0) {
            wsum[pix] += vwv;
            out_vw[((size_t)b*VV + v)*HWP + hw] = vwv;
        }
        __syncwarp();
    }

    float rws = 1.f / wsum[pix];
    float in8[8];
    #pragma unroll
    for (int g = 0; g < 8; g++) in8[g] = simsum[pix][lane][g] * rws;
    float sval = mlp8(sw[1], in8);
    g_s[(size_t)p*DD + lane] = sval;
}

// ---------------- K3: grid-sample + NN aggregation + softmax + depth ----------------
__global__ void __launch_bounds__(128)
k_final(const float* __restrict__ grid, const float* __restrict__ weight,
        const float* __restrict__ depth_sample, const int* __restrict__ is_inverse,
        float* __restrict__ out_depth, float* __restrict__ out_score) {
    int t = blockIdx.x * blockDim.x + threadIdx.x;
    int p = t >> 2;
    int q = t & 3;
    if (p >= BB*HWP) return;
    int b  = p / HWP;
    int hw = p - b * HWP;
    int h = hw / WW, w = hw - h * WW;

    float agg[4] = {0.f, 0.f, 0.f, 0.f};

    const float* wbase = weight + ((size_t)b*DD*NV)*HWP + hw + (size_t)(q*4)*NV*HWP;
    #pragma unroll
    for (int n = 0; n < NV; n++) {
        const float* gp = grid + (((size_t)b*NV*HH + n*HH + h)*WW + w)*2;
        float gx = __ldg(gp), gy = __ldg(gp + 1);
        float ix = ((gx + 1.f)*WW - 1.f) * 0.5f;
        float iy = ((gy + 1.f)*HH - 1.f) * 0.5f;
        float x0f = floorf(ix), y0f = floorf(iy);
        float fx = ix - x0f, fy = iy - y0f;
        int x0 = (int)x0f, y0 = (int)y0f;
        int xc0 = min(max(x0, 0), WW-1), xc1 = min(max(x0+1, 0), WW-1);
        int yc0 = min(max(y0, 0), HH-1), yc1 = min(max(y0+1, 0), HH-1);
        float w00 = (1.f-fx)*(1.f-fy), w01 = fx*(1.f-fy);
        float w10 = (1.f-fx)*fy,       w11 = fx*fy;
        float4 a00 = __ldg((const float4*)(g_s + ((size_t)b*HWP + yc0*WW + xc0)*DD) + q);
        float4 a01 = __ldg((const float4*)(g_s + ((size_t)b*HWP + yc0*WW + xc1)*DD) + q);
        float4 a10 = __ldg((const float4*)(g_s + ((size_t)b*HWP + yc1*WW + xc0)*DD) + q);
        float4 a11 = __ldg((const float4*)(g_s + ((size_t)b*HWP + yc1*WW + xc1)*DD) + q);
        float bx = w00*a00.x + w01*a01.x + w10*a10.x + w11*a11.x;
        float by = w00*a00.y + w01*a01.y + w10*a10.y + w11*a11.y;
        float bz = w00*a00.z + w01*a01.z + w10*a10.z + w11*a11.z;
        float bw = w00*a00.w + w01*a01.w + w10*a10.w + w11*a11.w;
        const float* wb = wbase + (size_t)n*HWP;
        agg[0] += __ldg(wb)                      * bx;
        agg[1] += __ldg(wb + (size_t)1*NV*HWP)   * by;
        agg[2] += __ldg(wb + (size_t)2*NV*HWP)   * bz;
        agg[3] += __ldg(wb + (size_t)3*NV*HWP)   * bw;
    }

    float m = fmaxf(fmaxf(agg[0], agg[1]), fmaxf(agg[2], agg[3]));
    m = fmaxf(m, __shfl_xor_sync(0xffffffffu, m, 1, 4));
    m = fmaxf(m, __shfl_xor_sync(0xffffffffu, m, 2, 4));
    float e[4]; float sum = 0.f;
    #pragma unroll
    for (int j = 0; j < 4; j++) { e[j] = expf(agg[j] - m); sum += e[j]; }
    sum += __shfl_xor_sync(0xffffffffu, sum, 1, 4);
    sum += __shfl_xor_sync(0xffffffffu, sum, 2, 4);
    float rs = 1.f / sum;

    const float* dsB = depth_sample + (size_t)b*DD*HWP + hw;
    float dep = 0.f;
    int inv = *is_inverse;
    #pragma unroll
    for (int j = 0; j < 4; j++) {
        float sc = e[j] * rs;
        int d = q*4 + j;
        out_score[((size_t)b*DD + d)*HWP + hw] = sc;
        if (inv) dep += (float)d * sc;
        else     dep += __ldg(dsB + (size_t)d*HWP) * sc;
    }
    dep += __shfl_xor_sync(0xffffffffu, dep, 1, 4);
    dep += __shfl_xor_sync(0xffffffffu, dep, 2, 4);
    if (q == 0) {
        if (inv) {
            float invmin = 1.f / __ldg(dsB + (size_t)(DD-1)*HWP);
            float invmax = 1.f / __ldg(dsB);
            dep = 1.f / (invmax + dep * (1.f/(float)(DD-1)) * (invmin - invmax));
        }
        out_depth[p] = dep;
    }
}

// ---------------- launch ----------------
extern "C" void kernel_launch(void* const* d_in, const int* in_sizes, int n_in,
                              void* d_out, int out_size) {
    const float* ref_feature  = (const float*)d_in[0];
    const float* src_features = (const float*)d_in[1];
    const float* ref_proj     = (const float*)d_in[2];
    const float* src_projs    = (const float*)d_in[3];
    const float* depth_sample = (const float*)d_in[4];
    const float* grid         = (const float*)d_in[5];
    const float* weight       = (const float*)d_in[6];
    const float* pw_w0  = (const float*)d_in[7];
    const float* pw_g0  = (const float*)d_in[8];
    const float* pw_b0  = (const float*)d_in[9];
    const float* pw_w1  = (const float*)d_in[10];
    const float* pw_g1  = (const float*)d_in[11];
    const float* pw_b1  = (const float*)d_in[12];
    const float* pw_w2  = (const float*)d_in[13];
    const float* pw_c2b = (const float*)d_in[14];
    const float* sn_w0  = (const float*)d_in[15];
    const float* sn_g0  = (const float*)d_in[16];
    const float* sn_b0  = (const float*)d_in[17];
    const float* sn_w1  = (const float*)d_in[18];
    const float* sn_g1  = (const float*)d_in[19];
    const float* sn_b1  = (const float*)d_in[20];
    const float* sn_w2  = (const float*)d_in[21];
    const float* sn_c2b = (const float*)d_in[22];
    const int*   is_inv = (const int*)d_in[23];

    float* out       = (float*)d_out;
    float* out_depth = out;
    float* out_score = out + (size_t)BB*HWP;
    float* out_vw    = out + (size_t)BB*HWP + (size_t)BB*DD*HWP;

    k_transpose<<<dim3(HWP/64, VV*BB + BB), 256>>>(ref_feature, src_features);
    k_proj<<<1, 32>>>(ref_proj, src_projs);
    k_main<<<BB*HWP/8, 128>>>(depth_sample,
                              pw_w0, pw_g0, pw_b0, pw_w1, pw_g1, pw_b1, pw_w2, pw_c2b,
                              sn_w0, sn_g0, sn_b0, sn_w1, sn_g1, sn_b1, sn_w2, sn_c2b,
                              out_vw);
    k_final<<<(BB*HWP*4 + 127)/128, 128>>>(grid, weight, depth_sample, is_inv,
                                           out_depth, out_score);
}

// round 4
// speedup vs baseline: 1.9398x; 1.5251x over previous
#include <cuda_runtime.h>
#include <cuda_fp16.h>
#include <math.h>
#include <stdint.h>

#define BB 2
#define CC 64
#define HH 128
#define WW 160
#define DD 16
#define VV 4
#define NV 9
#define HWP (HH*WW)

// ---------------- scratch (static device memory; no allocation) ----------------
__device__ __align__(16) __half g_srcT[(size_t)VV*BB*HWP*CC]; // fp16 [v*B+b][hw][c]
__device__ __align__(16) float  g_refT[(size_t)BB*HWP*CC];    // fp32 [b][hw][c]
__device__ float g_proj[VV*BB*12];
__device__ __align__(16) float g_s[(size_t)BB*HWP*DD];        // s channels-last [b][hw][d]

#define BNS 0.9999950000374997f

// ---------------- K0: transpose [C,HW] -> [HW,C]; src -> fp16, ref -> fp32 ----------------
__global__ void k_transpose(const float* __restrict__ ref, const float* __restrict__ src) {
    __shared__ float tile[64][65];
    int img = blockIdx.y;          // 0..7 = src v*B+b, 8..9 = ref b
    int hw0 = blockIdx.x * 64;
    const float* in = (img < VV*BB) ? (src + (size_t)img*CC*HWP)
                                    : (ref + (size_t)(img - VV*BB)*CC*HWP);
    for (int k = threadIdx.x; k < 64*64; k += blockDim.x) {
        int c = k >> 6, hwl = k & 63;
        tile[hwl][c] = in[(size_t)c*HWP + hw0 + hwl];
    }
    __syncthreads();
    if (img < VV*BB) {
        __half* out = g_srcT + (size_t)img*HWP*CC;
        for (int k = threadIdx.x; k < 64*64; k += blockDim.x) {
            int hwl = k >> 6, c = k & 63;
            out[(size_t)(hw0+hwl)*CC + c] = __float2half_rn(tile[hwl][c]);
        }
    } else {
        float* out = g_refT + (size_t)(img - VV*BB)*HWP*CC;
        for (int k = threadIdx.x; k < 64*64; k += blockDim.x) {
            int hwl = k >> 6, c = k & 63;
            out[(size_t)(hw0+hwl)*CC + c] = tile[hwl][c];
        }
    }
}

// ---------------- K1: proj = src_proj @ inv(ref_proj) ----------------
__global__ void k_proj(const float* __restrict__ ref_proj, const float* __restrict__ src_projs) {
    int t = threadIdx.x;
    if (t >= VV*BB) return;
    int v = t / BB, b = t % BB;
    float a[4][4], inv[4][4];
    #pragma unroll
    for (int i = 0; i < 4; i++)
        #pragma unroll
        for (int j = 0; j < 4; j++) {
            a[i][j] = ref_proj[b*16 + i*4 + j];
            inv[i][j] = (i == j) ? 1.f : 0.f;
        }
    for (int col = 0; col < 4; col++) {
        int piv = col; float best = fabsf(a[col][col]);
        for (int r = col+1; r < 4; r++) { float av = fabsf(a[r][col]); if (av > best) { best = av; piv = r; } }
        if (piv != col) {
            for (int j = 0; j < 4; j++) {
                float tm = a[col][j]; a[col][j] = a[piv][j]; a[piv][j] = tm;
                tm = inv[col][j]; inv[col][j] = inv[piv][j]; inv[piv][j] = tm;
            }
        }
        float dsc = 1.f / a[col][col];
        for (int j = 0; j < 4; j++) { a[col][j] *= dsc; inv[col][j] *= dsc; }
        for (int r = 0; r < 4; r++) {
            if (r == col) continue;
            float f = a[r][col];
            for (int j = 0; j < 4; j++) { a[r][j] -= f*a[col][j]; inv[r][j] -= f*inv[col][j]; }
        }
    }
    const float* s = src_projs + (size_t)(v*BB + b)*16;
    float* o = g_proj + (v*BB + b)*12;
    for (int i = 0; i < 3; i++)
        for (int j = 0; j < 4; j++) {
            float acc = 0.f;
            for (int k = 0; k < 4; k++) acc += s[i*4 + k] * inv[k][j];
            o[i*4 + j] = acc;
        }
}

// ---------------- fp16 packed MLP (8 -> 16 -> 8 -> 1) ----------------
// swh layout (uint32 = half2):
// [0:64)   W0: pair jp (0..7), input g (0..7): half2(w0[2jp][g], w0[2jp+1][g])
// [64:72)  gs0 pairs, [72:80) b0 pairs
// [80:144) W1: pair kp (0..3), input j (0..15): half2(w1[2kp][j], w1[2kp+1][j])
// [144:148) gs1 pairs, [148:152) b1 pairs, [152:156) w2 pairs, [156] c2b (float bits)
__device__ __forceinline__ __half2 u2h(uint32_t u) { return *reinterpret_cast<__half2*>(&u); }

__device__ __forceinline__ float mlp8h(const uint32_t* __restrict__ swh, const float in8[8]) {
    __half2 ind[8];
    #pragma unroll
    for (int g = 0; g < 8; g++) ind[g] = __float2half2_rn(in8[g]);
    const uint4* W0 = (const uint4*)swh;
    const uint4* W1 = (const uint4*)(swh + 80);
    const __half2 zero = __float2half2_rn(0.f);
    __half2 h1[8];
    #pragma unroll
    for (int jp = 0; jp < 8; jp++) {
        uint4 wa = W0[jp*2], wb = W0[jp*2+1];
        __half2 acc = __hmul2(u2h(wa.x), ind[0]);
        acc = __hfma2(u2h(wa.y), ind[1], acc);
        acc = __hfma2(u2h(wa.z), ind[2], acc);
        acc = __hfma2(u2h(wa.w), ind[3], acc);
        acc = __hfma2(u2h(wb.x), ind[4], acc);
        acc = __hfma2(u2h(wb.y), ind[5], acc);
        acc = __hfma2(u2h(wb.z), ind[6], acc);
        acc = __hfma2(u2h(wb.w), ind[7], acc);
        acc = __hfma2(acc, u2h(swh[64 + jp]), u2h(swh[72 + jp]));
        h1[jp] = __hmax2(acc, zero);
    }
    __half2 hd[16];
    #pragma unroll
    for (int jp = 0; jp < 8; jp++) {
        hd[2*jp]   = __low2half2(h1[jp]);
        hd[2*jp+1] = __high2half2(h1[jp]);
    }
    __half2 oacc = zero;
    #pragma unroll
    for (int kp = 0; kp < 4; kp++) {
        uint4 w0v = W1[kp*4], w1v = W1[kp*4+1], w2v = W1[kp*4+2], w3v = W1[kp*4+3];
        __half2 acc = __hmul2(u2h(w0v.x), hd[0]);
        acc = __hfma2(u2h(w0v.y), hd[1], acc);
        acc = __hfma2(u2h(w0v.z), hd[2], acc);
        acc = __hfma2(u2h(w0v.w), hd[3], acc);
        acc = __hfma2(u2h(w1v.x), hd[4], acc);
        acc = __hfma2(u2h(w1v.y), hd[5], acc);
        acc = __hfma2(u2h(w1v.z), hd[6], acc);
        acc = __hfma2(u2h(w1v.w), hd[7], acc);
        acc = __hfma2(u2h(w2v.x), hd[8], acc);
        acc = __hfma2(u2h(w2v.y), hd[9], acc);
        acc = __hfma2(u2h(w2v.z), hd[10], acc);
        acc = __hfma2(u2h(w2v.w), hd[11], acc);
        acc = __hfma2(u2h(w3v.x), hd[12], acc);
        acc = __hfma2(u2h(w3v.y), hd[13], acc);
        acc = __hfma2(u2h(w3v.z), hd[14], acc);
        acc = __hfma2(u2h(w3v.w), hd[15], acc);
        acc = __hfma2(acc, u2h(swh[144 + kp]), u2h(swh[148 + kp]));
        acc = __hmax2(acc, zero);
        oacc = __hfma2(u2h(swh[152 + kp]), acc, oacc);
    }
    float2 of = __half22float2(oacc);
    return of.x + of.y + __uint_as_float(swh[156]);
}

// ---------------- K2: warp + group correlation + pixelwise net + similarity net ----------------
// block = 128 threads = 16 pixels, 8 lanes per pixel; lane g owns correlation group g.
__global__ void __launch_bounds__(128)
k_main(const float* __restrict__ depth_sample,
       const float* __restrict__ pw_w0, const float* __restrict__ pw_g0, const float* __restrict__ pw_b0,
       const float* __restrict__ pw_w1, const float* __restrict__ pw_g1, const float* __restrict__ pw_b1,
       const float* __restrict__ pw_w2, const float* __restrict__ pw_c2b,
       const float* __restrict__ sn_w0, const float* __restrict__ sn_g0, const float* __restrict__ sn_b0,
       const float* __restrict__ sn_w1, const float* __restrict__ sn_g1, const float* __restrict__ sn_b1,
       const float* __restrict__ sn_w2, const float* __restrict__ sn_c2b,
       float* __restrict__ out_vw) {
    __shared__ __align__(16) uint32_t swh[2][160];
    __shared__ __align__(16) uint32_t scoord[16][16][8]; // [pix][d][4 idx + 4 w(half2dup)]
    __shared__ __align__(16) float simv[16][16][8];      // [pix][d][group]

    int tid = threadIdx.x;

    // pack fp16 MLP weights
    for (int i = tid; i < 320; i += 128) {
        int net = i / 160, j = i - net*160;
        const float* w0 = net ? sn_w0 : pw_w0;
        const float* g0 = net ? sn_g0 : pw_g0;
        const float* b0 = net ? sn_b0 : pw_b0;
        const float* w1 = net ? sn_w1 : pw_w1;
        const float* g1 = net ? sn_g1 : pw_g1;
        const float* b1 = net ? sn_b1 : pw_b1;
        const float* w2 = net ? sn_w2 : pw_w2;
        const float* cb = net ? sn_c2b : pw_c2b;
        uint32_t val;
        if (j < 64) {
            int jp = j >> 3, g = j & 7;
            __half2 h = __floats2half2_rn(w0[(2*jp)*8 + g], w0[(2*jp+1)*8 + g]);
            val = *reinterpret_cast<uint32_t*>(&h);
        } else if (j < 72) {
            int jp = j - 64;
            __half2 h = __floats2half2_rn(g0[2*jp]*BNS, g0[2*jp+1]*BNS);
            val = *reinterpret_cast<uint32_t*>(&h);
        } else if (j < 80) {
            int jp = j - 72;
            __half2 h = __floats2half2_rn(b0[2*jp], b0[2*jp+1]);
            val = *reinterpret_cast<uint32_t*>(&h);
        } else if (j < 144) {
            int idx = j - 80; int kp = idx >> 4, jj = idx & 15;
            __half2 h = __floats2half2_rn(w1[(2*kp)*16 + jj], w1[(2*kp+1)*16 + jj]);
            val = *reinterpret_cast<uint32_t*>(&h);
        } else if (j < 148) {
            int kp = j - 144;
            __half2 h = __floats2half2_rn(g1[2*kp]*BNS, g1[2*kp+1]*BNS);
            val = *reinterpret_cast<uint32_t*>(&h);
        } else if (j < 152) {
            int kp = j - 148;
            __half2 h = __floats2half2_rn(b1[2*kp], b1[2*kp+1]);
            val = *reinterpret_cast<uint32_t*>(&h);
        } else if (j < 156) {
            int kp = j - 152;
            __half2 h = __floats2half2_rn(w2[2*kp], w2[2*kp+1]);
            val = *reinterpret_cast<uint32_t*>(&h);
        } else {
            val = __float_as_uint(cb[0]);
        }
        swh[net][j] = val;
    }
    __syncthreads();

    int pix = tid >> 3;          // 0..15 within block
    int g   = tid & 7;           // group / lane within pixel
    int p = blockIdx.x * 16 + pix;
    int b  = p / HWP;
    int hw = p - b * HWP;
    int h = hw / WW, w = hw - h * WW;
    float wf = (float)w, hf = (float)h;

    // ref features for this lane's group (8 channels, fp32)
    const float4 rfa = *(const float4*)(g_refT + (size_t)p*CC + g*8);
    const float4 rfb = *(const float4*)(g_refT + (size_t)p*CC + g*8 + 4);

    // depths owned by this lane: d0 = g, d1 = g+8
    const float* dsB = depth_sample + (size_t)b*DD*HWP + hw;
    float dep0 = __ldg(dsB + (size_t)g*HWP);
    float dep1 = __ldg(dsB + (size_t)(g+8)*HWP);

    float acc0[8], acc1[8];      // simsum for depths g, g+8 (all groups)
    #pragma unroll
    for (int k = 0; k < 8; k++) { acc0[k] = 0.f; acc1[k] = 0.f; }
    float wsum = 0.f;

    for (int v = 0; v < VV; v++) {
        const float* M = g_proj + (v*BB + b)*12;
        float rx = M[0]*wf + M[1]*hf + M[2];
        float ry = M[4]*wf + M[5]*hf + M[6];
        float rz = M[8]*wf + M[9]*hf + M[10];
        float t0 = M[3], t1 = M[7], t2 = M[11];
        const __half* srcB = g_srcT + (size_t)(v*BB + b)*HWP*CC;

        // ---- Phase A: coords for depths g and g+8 ----
        #pragma unroll
        for (int k = 0; k < 2; k++) {
            float dep = k ? dep1 : dep0;
            int d = k ? (g+8) : g;
            float px = rx*dep + t0, py = ry*dep + t1, pz = rz*dep + t2;
            if (pz <= 0.001f) { px = (float)WW; py = (float)HH; pz = 1.f; }
            float ix = __fdividef(px, pz);
            float iy = __fdividef(py, pz);
            float x0f = floorf(ix), y0f = floorf(iy);
            float fx = ix - x0f, fy = iy - y0f;
            int x0 = (int)x0f, y0 = (int)y0f;
            int x1 = x0 + 1, y1 = y0 + 1;
            bool vx0 = (x0 >= 0) & (x0 < WW);
            bool vx1 = (x1 >= 0) & (x1 < WW);
            bool vy0 = (y0 >= 0) & (y0 < HH);
            bool vy1 = (y1 >= 0) & (y1 < HH);
            float w00 = (1.f-fx)*(1.f-fy) * (float)(vx0 && vy0);
            float w01 = fx*(1.f-fy)       * (float)(vx1 && vy0);
            float w10 = (1.f-fx)*fy       * (float)(vx0 && vy1);
            float w11 = fx*fy             * (float)(vx1 && vy1);
            int xc0 = min(max(x0, 0), WW-1), xc1 = min(max(x1, 0), WW-1);
            int yc0 = min(max(y0, 0), HH-1), yc1 = min(max(y1, 0), HH-1);
            int r0 = yc0*WW, r1 = yc1*WW;
            uint32_t* sc = scoord[pix][d];
            sc[0] = (uint32_t)(r0 + xc0);
            sc[1] = (uint32_t)(r0 + xc1);
            sc[2] = (uint32_t)(r1 + xc0);
            sc[3] = (uint32_t)(r1 + xc1);
            __half2 h00 = __float2half2_rn(w00);
            __half2 h01 = __float2half2_rn(w01);
            __half2 h10 = __float2half2_rn(w10);
            __half2 h11 = __float2half2_rn(w11);
            sc[4] = *reinterpret_cast<uint32_t*>(&h00);
            sc[5] = *reinterpret_cast<uint32_t*>(&h01);
            sc[6] = *reinterpret_cast<uint32_t*>(&h10);
            sc[7] = *reinterpret_cast<uint32_t*>(&h11);
        }
        __syncwarp();

        // ---- Phase B: all 16 depths, this lane = group g (8 channels, 16B/tap) ----
        #pragma unroll
        for (int d = 0; d < DD; d++) {
            uint4 ci = *(const uint4*)&scoord[pix][d][0];
            uint4 cw = *(const uint4*)&scoord[pix][d][4];
            uint4 u00 = __ldg((const uint4*)(srcB + (size_t)ci.x*CC) + g);
            uint4 u01 = __ldg((const uint4*)(srcB + (size_t)ci.y*CC) + g);
            uint4 u10 = __ldg((const uint4*)(srcB + (size_t)ci.z*CC) + g);
            uint4 u11 = __ldg((const uint4*)(srcB + (size_t)ci.w*CC) + g);
            __half2 w00 = u2h(cw.x), w01 = u2h(cw.y), w10 = u2h(cw.z), w11 = u2h(cw.w);
            __half2 m0 = __hmul2(u2h(u00.x), w00);
            __half2 m1 = __hmul2(u2h(u00.y), w00);
            __half2 m2 = __hmul2(u2h(u00.z), w00);
            __half2 m3 = __hmul2(u2h(u00.w), w00);
            m0 = __hfma2(u2h(u01.x), w01, m0);
            m1 = __hfma2(u2h(u01.y), w01, m1);
            m2 = __hfma2(u2h(u01.z), w01, m2);
            m3 = __hfma2(u2h(u01.w), w01, m3);
            m0 = __hfma2(u2h(u10.x), w10, m0);
            m1 = __hfma2(u2h(u10.y), w10, m1);
            m2 = __hfma2(u2h(u10.z), w10, m2);
            m3 = __hfma2(u2h(u10.w), w10, m3);
            m0 = __hfma2(u2h(u11.x), w11, m0);
            m1 = __hfma2(u2h(u11.y), w11, m1);
            m2 = __hfma2(u2h(u11.z), w11, m2);
            m3 = __hfma2(u2h(u11.w), w11, m3);
            float2 f0 = __half22float2(m0);
            float2 f1 = __half22float2(m1);
            float2 f2 = __half22float2(m2);
            float2 f3 = __half22float2(m3);
            float dot = f0.x*rfa.x + f0.y*rfa.y + f1.x*rfa.z + f1.y*rfa.w
                      + f2.x*rfb.x + f2.y*rfb.y + f3.x*rfb.z + f3.y*rfb.w;
            simv[pix][d][g] = dot * 0.125f;
        }
        __syncwarp();

        // ---- pixelwise net for depths g and g+8 ----
        float in0[8], in1[8];
        #pragma unroll
        for (int k = 0; k < 8; k++) { in0[k] = simv[pix][g][k]; in1[k] = simv[pix][g+8][k]; }
        float o0 = mlp8h(swh[0], in0);
        float o1 = mlp8h(swh[0], in1);
        float vw0 = 1.f / (1.f + expf(-o0));
        float vw1 = 1.f / (1.f + expf(-o1));
        float vmax = fmaxf(vw0, vw1);
        vmax = fmaxf(vmax, __shfl_xor_sync(0xffffffffu, vmax, 1, 8));
        vmax = fmaxf(vmax, __shfl_xor_sync(0xffffffffu, vmax, 2, 8));
        vmax = fmaxf(vmax, __shfl_xor_sync(0xffffffffu, vmax, 4, 8));
        #pragma unroll
        for (int k = 0; k < 8; k++) { acc0[k] += in0[k]*vmax; acc1[k] += in1[k]*vmax; }
        wsum += vmax;
        if (g == 0) out_vw[((size_t)b*VV + v)*HWP + hw] = vmax;
        __syncwarp();
    }

    float rws = 1.f / wsum;
    float in0[8], in1[8];
    #pragma unroll
    for (int k = 0; k < 8; k++) { in0[k] = acc0[k]*rws; in1[k] = acc1[k]*rws; }
    float s0 = mlp8h(swh[1], in0);
    float s1 = mlp8h(swh[1], in1);
    g_s[(size_t)p*DD + g]     = s0;
    g_s[(size_t)p*DD + g + 8] = s1;
}

// ---------------- K3: grid-sample + NN aggregation + softmax + depth ----------------
__global__ void __launch_bounds__(128)
k_final(const float* __restrict__ grid, const float* __restrict__ weight,
        const float* __restrict__ depth_sample, const int* __restrict__ is_inverse,
        float* __restrict__ out_depth, float* __restrict__ out_score) {
    int t = blockIdx.x * blockDim.x + threadIdx.x;
    int p = t >> 2;
    int q = t & 3;
    if (p >= BB*HWP) return;
    int b  = p / HWP;
    int hw = p - b * HWP;
    int h = hw / WW, w = hw - h * WW;

    float agg[4] = {0.f, 0.f, 0.f, 0.f};

    const float* wbase = weight + ((size_t)b*DD*NV)*HWP + hw + (size_t)(q*4)*NV*HWP;
    #pragma unroll
    for (int n = 0; n < NV; n++) {
        const float* gp = grid + (((size_t)b*NV*HH + n*HH + h)*WW + w)*2;
        float gx = __ldg(gp), gy = __ldg(gp + 1);
        float ix = ((gx + 1.f)*WW - 1.f) * 0.5f;
        float iy = ((gy + 1.f)*HH - 1.f) * 0.5f;
        float x0f = floorf(ix), y0f = floorf(iy);
        float fx = ix - x0f, fy = iy - y0f;
        int x0 = (int)x0f, y0 = (int)y0f;
        int xc0 = min(max(x0, 0), WW-1), xc1 = min(max(x0+1, 0), WW-1);
        int yc0 = min(max(y0, 0), HH-1), yc1 = min(max(y0+1, 0), HH-1);
        float w00 = (1.f-fx)*(1.f-fy), w01 = fx*(1.f-fy);
        float w10 = (1.f-fx)*fy,       w11 = fx*fy;
        float4 a00 = __ldg((const float4*)(g_s + ((size_t)b*HWP + yc0*WW + xc0)*DD) + q);
        float4 a01 = __ldg((const float4*)(g_s + ((size_t)b*HWP + yc0*WW + xc1)*DD) + q);
        float4 a10 = __ldg((const float4*)(g_s + ((size_t)b*HWP + yc1*WW + xc0)*DD) + q);
        float4 a11 = __ldg((const float4*)(g_s + ((size_t)b*HWP + yc1*WW + xc1)*DD) + q);
        float bx = w00*a00.x + w01*a01.x + w10*a10.x + w11*a11.x;
        float by = w00*a00.y + w01*a01.y + w10*a10.y + w11*a11.y;
        float bz = w00*a00.z + w01*a01.z + w10*a10.z + w11*a11.z;
        float bw = w00*a00.w + w01*a01.w + w10*a10.w + w11*a11.w;
        const float* wb = wbase + (size_t)n*HWP;
        agg[0] += __ldg(wb)                      * bx;
        agg[1] += __ldg(wb + (size_t)1*NV*HWP)   * by;
        agg[2] += __ldg(wb + (size_t)2*NV*HWP)   * bz;
        agg[3] += __ldg(wb + (size_t)3*NV*HWP)   * bw;
    }

    float m = fmaxf(fmaxf(agg[0], agg[1]), fmaxf(agg[2], agg[3]));
    m = fmaxf(m, __shfl_xor_sync(0xffffffffu, m, 1, 4));
    m = fmaxf(m, __shfl_xor_sync(0xffffffffu, m, 2, 4));
    float e[4]; float sum = 0.f;
    #pragma unroll
    for (int j = 0; j < 4; j++) { e[j] = expf(agg[j] - m); sum += e[j]; }
    sum += __shfl_xor_sync(0xffffffffu, sum, 1, 4);
    sum += __shfl_xor_sync(0xffffffffu, sum, 2, 4);
    float rs = 1.f / sum;

    const float* dsB = depth_sample + (size_t)b*DD*HWP + hw;
    float dep = 0.f;
    int inv = *is_inverse;
    #pragma unroll
    for (int j = 0; j < 4; j++) {
        float sc = e[j] * rs;
        int d = q*4 + j;
        out_score[((size_t)b*DD + d)*HWP + hw] = sc;
        if (inv) dep += (float)d * sc;
        else     dep += __ldg(dsB + (size_t)d*HWP) * sc;
    }
    dep += __shfl_xor_sync(0xffffffffu, dep, 1, 4);
    dep += __shfl_xor_sync(0xffffffffu, dep, 2, 4);
    if (q == 0) {
        if (inv) {
            float invmin = 1.f / __ldg(dsB + (size_t)(DD-1)*HWP);
            float invmax = 1.f / __ldg(dsB);
            dep = 1.f / (invmax + dep * (1.f/(float)(DD-1)) * (invmin - invmax));
        }
        out_depth[p] = dep;
    }
}

// ---------------- launch ----------------
extern "C" void kernel_launch(void* const* d_in, const int* in_sizes, int n_in,
                              void* d_out, int out_size) {
    const float* ref_feature  = (const float*)d_in[0];
    const float* src_features = (const float*)d_in[1];
    const float* ref_proj     = (const float*)d_in[2];
    const float* src_projs    = (const float*)d_in[3];
    const float* depth_sample = (const float*)d_in[4];
    const float* grid         = (const float*)d_in[5];
    const float* weight       = (const float*)d_in[6];
    const float* pw_w0  = (const float*)d_in[7];
    const float* pw_g0  = (const float*)d_in[8];
    const float* pw_b0  = (const float*)d_in[9];
    const float* pw_w1  = (const float*)d_in[10];
    const float* pw_g1  = (const float*)d_in[11];
    const float* pw_b1  = (const float*)d_in[12];
    const float* pw_w2  = (const float*)d_in[13];
    const float* pw_c2b = (const float*)d_in[14];
    const float* sn_w0  = (const float*)d_in[15];
    const float* sn_g0  = (const float*)d_in[16];
    const float* sn_b0  = (const float*)d_in[17];
    const float* sn_w1  = (const float*)d_in[18];
    const float* sn_g1  = (const float*)d_in[19];
    const float* sn_b1  = (const float*)d_in[20];
    const float* sn_w2  = (const float*)d_in[21];
    const float* sn_c2b = (const float*)d_in[22];
    const int*   is_inv = (const int*)d_in[23];

    float* out       = (float*)d_out;
    float* out_depth = out;
    float* out_score = out + (size_t)BB*HWP;
    float* out_vw    = out + (size_t)BB*HWP + (size_t)BB*DD*HWP;

    k_transpose<<<dim3(HWP/64, VV*BB + BB), 256>>>(ref_feature, src_features);
    k_proj<<<1, 32>>>(ref_proj, src_projs);
    k_main<<<BB*HWP/16, 128>>>(depth_sample,
                               pw_w0, pw_g0, pw_b0, pw_w1, pw_g1, pw_b1, pw_w2, pw_c2b,
                               sn_w0, sn_g0, sn_b0, sn_w1, sn_g1, sn_b1, sn_w2, sn_c2b,
                               out_vw);
    k_final<<<(BB*HWP*4 + 127)/128, 128>>>(grid, weight, depth_sample, is_inv,
                                           out_depth, out_score);
}

// round 5
// speedup vs baseline: 1.9416x; 1.0009x over previous
#include <cuda_runtime.h>
#include <cuda_fp16.h>
#include <math.h>
#include <stdint.h>

#define BB 2
#define CC 64
#define HH 128
#define WW 160
#define DD 16
#define VV 4
#define NV 9
#define HWP (HH*WW)

// ---------------- scratch (static device memory; no allocation) ----------------
__device__ __align__(16) __half g_srcT[(size_t)VV*BB*HWP*CC]; // fp16 [v*B+b][hw][c]
__device__ __align__(16) float  g_refT[(size_t)BB*HWP*CC];    // fp32 [b][hw][c]
__device__ float g_proj[VV*BB*12];
__device__ __align__(16) float g_s[(size_t)BB*HWP*DD];        // s channels-last [b][hw][d]

#define BNS 0.9999950000374997f

// ---------------- K0: transpose [C,HW] -> [HW,C]; src -> fp16, ref -> fp32 ----------------
__global__ void k_transpose(const float* __restrict__ ref, const float* __restrict__ src) {
    __shared__ float tile[64][65];
    int img = blockIdx.y;          // 0..7 = src v*B+b, 8..9 = ref b
    int hw0 = blockIdx.x * 64;
    const float* in = (img < VV*BB) ? (src + (size_t)img*CC*HWP)
                                    : (ref + (size_t)(img - VV*BB)*CC*HWP);
    for (int k = threadIdx.x; k < 64*64; k += blockDim.x) {
        int c = k >> 6, hwl = k & 63;
        tile[hwl][c] = in[(size_t)c*HWP + hw0 + hwl];
    }
    __syncthreads();
    if (img < VV*BB) {
        __half2* out = (__half2*)(g_srcT + (size_t)img*HWP*CC);
        for (int k = threadIdx.x; k < 64*32; k += blockDim.x) {
            int hwl = k >> 5, cp = k & 31;
            out[(size_t)(hw0+hwl)*(CC/2) + cp] =
                __floats2half2_rn(tile[hwl][2*cp], tile[hwl][2*cp+1]);
        }
    } else {
        float* out = g_refT + (size_t)(img - VV*BB)*HWP*CC;
        for (int k = threadIdx.x; k < 64*64; k += blockDim.x) {
            int hwl = k >> 6, c = k & 63;
            out[(size_t)(hw0+hwl)*CC + c] = tile[hwl][c];
        }
    }
}

// ---------------- K1: proj = src_proj @ inv(ref_proj) ----------------
__global__ void k_proj(const float* __restrict__ ref_proj, const float* __restrict__ src_projs) {
    int t = threadIdx.x;
    if (t >= VV*BB) return;
    int v = t / BB, b = t % BB;
    float a[4][4], inv[4][4];
    #pragma unroll
    for (int i = 0; i < 4; i++)
        #pragma unroll
        for (int j = 0; j < 4; j++) {
            a[i][j] = ref_proj[b*16 + i*4 + j];
            inv[i][j] = (i == j) ? 1.f : 0.f;
        }
    for (int col = 0; col < 4; col++) {
        int piv = col; float best = fabsf(a[col][col]);
        for (int r = col+1; r < 4; r++) { float av = fabsf(a[r][col]); if (av > best) { best = av; piv = r; } }
        if (piv != col) {
            for (int j = 0; j < 4; j++) {
                float tm = a[col][j]; a[col][j] = a[piv][j]; a[piv][j] = tm;
                tm = inv[col][j]; inv[col][j] = inv[piv][j]; inv[piv][j] = tm;
            }
        }
        float dsc = 1.f / a[col][col];
        for (int j = 0; j < 4; j++) { a[col][j] *= dsc; inv[col][j] *= dsc; }
        for (int r = 0; r < 4; r++) {
            if (r == col) continue;
            float f = a[r][col];
            for (int j = 0; j < 4; j++) { a[r][j] -= f*a[col][j]; inv[r][j] -= f*inv[col][j]; }
        }
    }
    const float* s = src_projs + (size_t)(v*BB + b)*16;
    float* o = g_proj + (v*BB + b)*12;
    for (int i = 0; i < 3; i++)
        for (int j = 0; j < 4; j++) {
            float acc = 0.f;
            for (int k = 0; k < 4; k++) acc += s[i*4 + k] * inv[k][j];
            o[i*4 + j] = acc;
        }
}

// ---------------- fp16 packed MLP (8 -> 16 -> 8 -> 1) ----------------
// swh layout (uint32 = half2):
// [0:64)   W0: pair jp (0..7), input g (0..7): half2(w0[2jp][g], w0[2jp+1][g])
// [64:72)  gs0 pairs, [72:80) b0 pairs
// [80:144) W1: pair kp (0..3), input j (0..15): half2(w1[2kp][j], w1[2kp+1][j])
// [144:148) gs1 pairs, [148:152) b1 pairs, [152:156) w2 pairs, [156] c2b (float bits)
__device__ __forceinline__ __half2 u2h(uint32_t u) { return *reinterpret_cast<__half2*>(&u); }

__device__ __forceinline__ float mlp8h(const uint32_t* __restrict__ swh, const float in8[8]) {
    __half2 ind[8];
    #pragma unroll
    for (int g = 0; g < 8; g++) ind[g] = __float2half2_rn(in8[g]);
    const uint4* W0 = (const uint4*)swh;
    const uint4* W1 = (const uint4*)(swh + 80);
    const __half2 zero = __float2half2_rn(0.f);
    __half2 h1[8];
    #pragma unroll
    for (int jp = 0; jp < 8; jp++) {
        uint4 wa = W0[jp*2], wb = W0[jp*2+1];
        __half2 acc = __hmul2(u2h(wa.x), ind[0]);
        acc = __hfma2(u2h(wa.y), ind[1], acc);
        acc = __hfma2(u2h(wa.z), ind[2], acc);
        acc = __hfma2(u2h(wa.w), ind[3], acc);
        acc = __hfma2(u2h(wb.x), ind[4], acc);
        acc = __hfma2(u2h(wb.y), ind[5], acc);
        acc = __hfma2(u2h(wb.z), ind[6], acc);
        acc = __hfma2(u2h(wb.w), ind[7], acc);
        acc = __hfma2(acc, u2h(swh[64 + jp]), u2h(swh[72 + jp]));
        h1[jp] = __hmax2(acc, zero);
    }
    __half2 hd[16];
    #pragma unroll
    for (int jp = 0; jp < 8; jp++) {
        hd[2*jp]   = __low2half2(h1[jp]);
        hd[2*jp+1] = __high2half2(h1[jp]);
    }
    __half2 oacc = zero;
    #pragma unroll
    for (int kp = 0; kp < 4; kp++) {
        uint4 w0v = W1[kp*4], w1v = W1[kp*4+1], w2v = W1[kp*4+2], w3v = W1[kp*4+3];
        __half2 acc = __hmul2(u2h(w0v.x), hd[0]);
        acc = __hfma2(u2h(w0v.y), hd[1], acc);
        acc = __hfma2(u2h(w0v.z), hd[2], acc);
        acc = __hfma2(u2h(w0v.w), hd[3], acc);
        acc = __hfma2(u2h(w1v.x), hd[4], acc);
        acc = __hfma2(u2h(w1v.y), hd[5], acc);
        acc = __hfma2(u2h(w1v.z), hd[6], acc);
        acc = __hfma2(u2h(w1v.w), hd[7], acc);
        acc = __hfma2(u2h(w2v.x), hd[8], acc);
        acc = __hfma2(u2h(w2v.y), hd[9], acc);
        acc = __hfma2(u2h(w2v.z), hd[10], acc);
        acc = __hfma2(u2h(w2v.w), hd[11], acc);
        acc = __hfma2(u2h(w3v.x), hd[12], acc);
        acc = __hfma2(u2h(w3v.y), hd[13], acc);
        acc = __hfma2(u2h(w3v.z), hd[14], acc);
        acc = __hfma2(u2h(w3v.w), hd[15], acc);
        acc = __hfma2(acc, u2h(swh[144 + kp]), u2h(swh[148 + kp]));
        acc = __hmax2(acc, zero);
        oacc = __hfma2(u2h(swh[152 + kp]), acc, oacc);
    }
    float2 of = __half22float2(oacc);
    return of.x + of.y + __uint_as_float(swh[156]);
}

// ---------------- K2: warp + group correlation + pixelwise net + similarity net ----------------
// block = 128 threads = 16 pixels, 8 lanes per pixel; lane g owns correlation group g.
__global__ void __launch_bounds__(128)
k_main(const float* __restrict__ depth_sample,
       const float* __restrict__ pw_w0, const float* __restrict__ pw_g0, const float* __restrict__ pw_b0,
       const float* __restrict__ pw_w1, const float* __restrict__ pw_g1, const float* __restrict__ pw_b1,
       const float* __restrict__ pw_w2, const float* __restrict__ pw_c2b,
       const float* __restrict__ sn_w0, const float* __restrict__ sn_g0, const float* __restrict__ sn_b0,
       const float* __restrict__ sn_w1, const float* __restrict__ sn_g1, const float* __restrict__ sn_b1,
       const float* __restrict__ sn_w2, const float* __restrict__ sn_c2b,
       float* __restrict__ out_vw) {
    __shared__ __align__(16) uint32_t swh[2][160];
    __shared__ __align__(16) uint32_t scoord[16][16][8]; // [pix][d][4 idx + 4 w(half2dup)]
    __shared__ __align__(16) float simv[16][16][8];      // [pix][d][group]

    int tid = threadIdx.x;

    // pack fp16 MLP weights
    for (int i = tid; i < 320; i += 128) {
        int net = i / 160, j = i - net*160;
        const float* w0 = net ? sn_w0 : pw_w0;
        const float* g0 = net ? sn_g0 : pw_g0;
        const float* b0 = net ? sn_b0 : pw_b0;
        const float* w1 = net ? sn_w1 : pw_w1;
        const float* g1 = net ? sn_g1 : pw_g1;
        const float* b1 = net ? sn_b1 : pw_b1;
        const float* w2 = net ? sn_w2 : pw_w2;
        const float* cb = net ? sn_c2b : pw_c2b;
        uint32_t val;
        if (j < 64) {
            int jp = j >> 3, g = j & 7;
            __half2 h = __floats2half2_rn(w0[(2*jp)*8 + g], w0[(2*jp+1)*8 + g]);
            val = *reinterpret_cast<uint32_t*>(&h);
        } else if (j < 72) {
            int jp = j - 64;
            __half2 h = __floats2half2_rn(g0[2*jp]*BNS, g0[2*jp+1]*BNS);
            val = *reinterpret_cast<uint32_t*>(&h);
        } else if (j < 80) {
            int jp = j - 72;
            __half2 h = __floats2half2_rn(b0[2*jp], b0[2*jp+1]);
            val = *reinterpret_cast<uint32_t*>(&h);
        } else if (j < 144) {
            int idx = j - 80; int kp = idx >> 4, jj = idx & 15;
            __half2 h = __floats2half2_rn(w1[(2*kp)*16 + jj], w1[(2*kp+1)*16 + jj]);
            val = *reinterpret_cast<uint32_t*>(&h);
        } else if (j < 148) {
            int kp = j - 144;
            __half2 h = __floats2half2_rn(g1[2*kp]*BNS, g1[2*kp+1]*BNS);
            val = *reinterpret_cast<uint32_t*>(&h);
        } else if (j < 152) {
            int kp = j - 148;
            __half2 h = __floats2half2_rn(b1[2*kp], b1[2*kp+1]);
            val = *reinterpret_cast<uint32_t*>(&h);
        } else if (j < 156) {
            int kp = j - 152;
            __half2 h = __floats2half2_rn(w2[2*kp], w2[2*kp+1]);
            val = *reinterpret_cast<uint32_t*>(&h);
        } else {
            val = __float_as_uint(cb[0]);
        }
        swh[net][j] = val;
    }
    __syncthreads();

    int pix = tid >> 3;          // 0..15 within block
    int g   = tid & 7;           // group / lane within pixel
    int p = blockIdx.x * 16 + pix;
    int b  = p / HWP;
    int hw = p - b * HWP;
    int h = hw / WW, w = hw - h * WW;
    float wf = (float)w, hf = (float)h;

    // ref features for this lane's group (8 channels), pre-converted to half2
    const float4 rfa = *(const float4*)(g_refT + (size_t)p*CC + g*8);
    const float4 rfb = *(const float4*)(g_refT + (size_t)p*CC + g*8 + 4);
    __half2 rh0 = __floats2half2_rn(rfa.x, rfa.y);
    __half2 rh1 = __floats2half2_rn(rfa.z, rfa.w);
    __half2 rh2 = __floats2half2_rn(rfb.x, rfb.y);
    __half2 rh3 = __floats2half2_rn(rfb.z, rfb.w);

    // depths owned by this lane: d0 = g, d1 = g+8
    const float* dsB = depth_sample + (size_t)b*DD*HWP + hw;
    float dep0 = __ldg(dsB + (size_t)g*HWP);
    float dep1 = __ldg(dsB + (size_t)(g+8)*HWP);

    float acc0[8], acc1[8];      // simsum for depths g, g+8 (all groups)
    #pragma unroll
    for (int k = 0; k < 8; k++) { acc0[k] = 0.f; acc1[k] = 0.f; }
    float wsum = 0.f;

    for (int v = 0; v < VV; v++) {
        const float* M = g_proj + (v*BB + b)*12;
        float rx = M[0]*wf + M[1]*hf + M[2];
        float ry = M[4]*wf + M[5]*hf + M[6];
        float rz = M[8]*wf + M[9]*hf + M[10];
        float t0 = M[3], t1 = M[7], t2 = M[11];
        const __half* srcB = g_srcT + (size_t)(v*BB + b)*HWP*CC;

        // ---- Phase A: coords for depths g and g+8 ----
        #pragma unroll
        for (int k = 0; k < 2; k++) {
            float dep = k ? dep1 : dep0;
            int d = k ? (g+8) : g;
            float px = rx*dep + t0, py = ry*dep + t1, pz = rz*dep + t2;
            if (pz <= 0.001f) { px = (float)WW; py = (float)HH; pz = 1.f; }
            float ix = __fdividef(px, pz);
            float iy = __fdividef(py, pz);
            float x0f = floorf(ix), y0f = floorf(iy);
            float fx = ix - x0f, fy = iy - y0f;
            int x0 = (int)x0f, y0 = (int)y0f;
            int x1 = x0 + 1, y1 = y0 + 1;
            bool vx0 = (x0 >= 0) & (x0 < WW);
            bool vx1 = (x1 >= 0) & (x1 < WW);
            bool vy0 = (y0 >= 0) & (y0 < HH);
            bool vy1 = (y1 >= 0) & (y1 < HH);
            float w00 = (1.f-fx)*(1.f-fy) * (float)(vx0 && vy0);
            float w01 = fx*(1.f-fy)       * (float)(vx1 && vy0);
            float w10 = (1.f-fx)*fy       * (float)(vx0 && vy1);
            float w11 = fx*fy             * (float)(vx1 && vy1);
            int xc0 = min(max(x0, 0), WW-1), xc1 = min(max(x1, 0), WW-1);
            int yc0 = min(max(y0, 0), HH-1), yc1 = min(max(y1, 0), HH-1);
            int r0 = yc0*WW, r1 = yc1*WW;
            uint32_t* sc = scoord[pix][d];
            sc[0] = (uint32_t)(r0 + xc0);
            sc[1] = (uint32_t)(r0 + xc1);
            sc[2] = (uint32_t)(r1 + xc0);
            sc[3] = (uint32_t)(r1 + xc1);
            __half2 h00 = __float2half2_rn(w00);
            __half2 h01 = __float2half2_rn(w01);
            __half2 h10 = __float2half2_rn(w10);
            __half2 h11 = __float2half2_rn(w11);
            sc[4] = *reinterpret_cast<uint32_t*>(&h00);
            sc[5] = *reinterpret_cast<uint32_t*>(&h01);
            sc[6] = *reinterpret_cast<uint32_t*>(&h10);
            sc[7] = *reinterpret_cast<uint32_t*>(&h11);
        }
        __syncwarp();

        // ---- Phase B: all 16 depths, this lane = group g (8 channels, 16B/tap) ----
        #pragma unroll
        for (int d = 0; d < DD; d++) {
            uint4 ci = *(const uint4*)&scoord[pix][d][0];
            uint4 cw = *(const uint4*)&scoord[pix][d][4];
            uint4 u00 = __ldg((const uint4*)(srcB + (size_t)ci.x*CC) + g);
            uint4 u01 = __ldg((const uint4*)(srcB + (size_t)ci.y*CC) + g);
            uint4 u10 = __ldg((const uint4*)(srcB + (size_t)ci.z*CC) + g);
            uint4 u11 = __ldg((const uint4*)(srcB + (size_t)ci.w*CC) + g);
            __half2 w00 = u2h(cw.x), w01 = u2h(cw.y), w10 = u2h(cw.z), w11 = u2h(cw.w);
            __half2 m0 = __hmul2(u2h(u00.x), w00);
            __half2 m1 = __hmul2(u2h(u00.y), w00);
            __half2 m2 = __hmul2(u2h(u00.z), w00);
            __half2 m3 = __hmul2(u2h(u00.w), w00);
            m0 = __hfma2(u2h(u01.x), w01, m0);
            m1 = __hfma2(u2h(u01.y), w01, m1);
            m2 = __hfma2(u2h(u01.z), w01, m2);
            m3 = __hfma2(u2h(u01.w), w01, m3);
            m0 = __hfma2(u2h(u10.x), w10, m0);
            m1 = __hfma2(u2h(u10.y), w10, m1);
            m2 = __hfma2(u2h(u10.z), w10, m2);
            m3 = __hfma2(u2h(u10.w), w10, m3);
            m0 = __hfma2(u2h(u11.x), w11, m0);
            m1 = __hfma2(u2h(u11.y), w11, m1);
            m2 = __hfma2(u2h(u11.z), w11, m2);
            m3 = __hfma2(u2h(u11.w), w11, m3);
            // fp16 group dot with ref
            __half2 da = __hmul2(m0, rh0);
            da = __hfma2(m1, rh1, da);
            da = __hfma2(m2, rh2, da);
            da = __hfma2(m3, rh3, da);
            float2 df = __half22float2(da);
            simv[pix][d][g] = (df.x + df.y) * 0.125f;
        }
        __syncwarp();

        // ---- pixelwise net for depths g and g+8 ----
        float in0[8], in1[8];
        #pragma unroll
        for (int k = 0; k < 8; k++) { in0[k] = simv[pix][g][k]; in1[k] = simv[pix][g+8][k]; }
        float o0 = mlp8h(swh[0], in0);
        float o1 = mlp8h(swh[0], in1);
        float vw0 = __frcp_rn(1.f + __expf(-o0));
        float vw1 = __frcp_rn(1.f + __expf(-o1));
        float vmax = fmaxf(vw0, vw1);
        vmax = fmaxf(vmax, __shfl_xor_sync(0xffffffffu, vmax, 1, 8));
        vmax = fmaxf(vmax, __shfl_xor_sync(0xffffffffu, vmax, 2, 8));
        vmax = fmaxf(vmax, __shfl_xor_sync(0xffffffffu, vmax, 4, 8));
        #pragma unroll
        for (int k = 0; k < 8; k++) { acc0[k] += in0[k]*vmax; acc1[k] += in1[k]*vmax; }
        wsum += vmax;
        if (g == 0) out_vw[((size_t)b*VV + v)*HWP + hw] = vmax;
        __syncwarp();
    }

    float rws = 1.f / wsum;
    float in0[8], in1[8];
    #pragma unroll
    for (int k = 0; k < 8; k++) { in0[k] = acc0[k]*rws; in1[k] = acc1[k]*rws; }
    float s0 = mlp8h(swh[1], in0);
    float s1 = mlp8h(swh[1], in1);
    g_s[(size_t)p*DD + g]     = s0;
    g_s[(size_t)p*DD + g + 8] = s1;
}

// ---------------- K3: grid-sample + NN aggregation + softmax + depth ----------------
__global__ void __launch_bounds__(128)
k_final(const float* __restrict__ grid, const float* __restrict__ weight,
        const float* __restrict__ depth_sample, const int* __restrict__ is_inverse,
        float* __restrict__ out_depth, float* __restrict__ out_score) {
    int t = blockIdx.x * blockDim.x + threadIdx.x;
    int p = t >> 2;
    int q = t & 3;
    if (p >= BB*HWP) return;
    int b  = p / HWP;
    int hw = p - b * HWP;
    int h = hw / WW, w = hw - h * WW;

    float agg[4] = {0.f, 0.f, 0.f, 0.f};

    const float* wbase = weight + ((size_t)b*DD*NV)*HWP + hw + (size_t)(q*4)*NV*HWP;
    #pragma unroll
    for (int n = 0; n < NV; n++) {
        const float* gp = grid + (((size_t)b*NV*HH + n*HH + h)*WW + w)*2;
        float gx = __ldg(gp), gy = __ldg(gp + 1);
        float ix = ((gx + 1.f)*WW - 1.f) * 0.5f;
        float iy = ((gy + 1.f)*HH - 1.f) * 0.5f;
        float x0f = floorf(ix), y0f = floorf(iy);
        float fx = ix - x0f, fy = iy - y0f;
        int x0 = (int)x0f, y0 = (int)y0f;
        int xc0 = min(max(x0, 0), WW-1), xc1 = min(max(x0+1, 0), WW-1);
        int yc0 = min(max(y0, 0), HH-1), yc1 = min(max(y0+1, 0), HH-1);
        float w00 = (1.f-fx)*(1.f-fy), w01 = fx*(1.f-fy);
        float w10 = (1.f-fx)*fy,       w11 = fx*fy;
        float4 a00 = __ldg((const float4*)(g_s + ((size_t)b*HWP + yc0*WW + xc0)*DD) + q);
        float4 a01 = __ldg((const float4*)(g_s + ((size_t)b*HWP + yc0*WW + xc1)*DD) + q);
        float4 a10 = __ldg((const float4*)(g_s + ((size_t)b*HWP + yc1*WW + xc0)*DD) + q);
        float4 a11 = __ldg((const float4*)(g_s + ((size_t)b*HWP + yc1*WW + xc1)*DD) + q);
        float bx = w00*a00.x + w01*a01.x + w10*a10.x + w11*a11.x;
        float by = w00*a00.y + w01*a01.y + w10*a10.y + w11*a11.y;
        float bz = w00*a00.z + w01*a01.z + w10*a10.z + w11*a11.z;
        float bw = w00*a00.w + w01*a01.w + w10*a10.w + w11*a11.w;
        const float* wb = wbase + (size_t)n*HWP;
        agg[0] += __ldg(wb)                      * bx;
        agg[1] += __ldg(wb + (size_t)1*NV*HWP)   * by;
        agg[2] += __ldg(wb + (size_t)2*NV*HWP)   * bz;
        agg[3] += __ldg(wb + (size_t)3*NV*HWP)   * bw;
    }

    float m = fmaxf(fmaxf(agg[0], agg[1]), fmaxf(agg[2], agg[3]));
    m = fmaxf(m, __shfl_xor_sync(0xffffffffu, m, 1, 4));
    m = fmaxf(m, __shfl_xor_sync(0xffffffffu, m, 2, 4));
    float e[4]; float sum = 0.f;
    #pragma unroll
    for (int j = 0; j < 4; j++) { e[j] = __expf(agg[j] - m); sum += e[j]; }
    sum += __shfl_xor_sync(0xffffffffu, sum, 1, 4);
    sum += __shfl_xor_sync(0xffffffffu, sum, 2, 4);
    float rs = 1.f / sum;

    const float* dsB = depth_sample + (size_t)b*DD*HWP + hw;
    float dep = 0.f;
    int inv = *is_inverse;
    #pragma unroll
    for (int j = 0; j < 4; j++) {
        float sc = e[j] * rs;
        int d = q*4 + j;
        out_score[((size_t)b*DD + d)*HWP + hw] = sc;
        if (inv) dep += (float)d * sc;
        else     dep += __ldg(dsB + (size_t)d*HWP) * sc;
    }
    dep += __shfl_xor_sync(0xffffffffu, dep, 1, 4);
    dep += __shfl_xor_sync(0xffffffffu, dep, 2, 4);
    if (q == 0) {
        if (inv) {
            float invmin = 1.f / __ldg(dsB + (size_t)(DD-1)*HWP);
            float invmax = 1.f / __ldg(dsB);
            dep = 1.f / (invmax + dep * (1.f/(float)(DD-1)) * (invmin - invmax));
        }
        out_depth[p] = dep;
    }
}

// ---------------- launch ----------------
extern "C" void kernel_launch(void* const* d_in, const int* in_sizes, int n_in,
                              void* d_out, int out_size) {
    const float* ref_feature  = (const float*)d_in[0];
    const float* src_features = (const float*)d_in[1];
    const float* ref_proj     = (const float*)d_in[2];
    const float* src_projs    = (const float*)d_in[3];
    const float* depth_sample = (const float*)d_in[4];
    const float* grid         = (const float*)d_in[5];
    const float* weight       = (const float*)d_in[6];
    const float* pw_w0  = (const float*)d_in[7];
    const float* pw_g0  = (const float*)d_in[8];
    const float* pw_b0  = (const float*)d_in[9];
    const float* pw_w1  = (const float*)d_in[10];
    const float* pw_g1  = (const float*)d_in[11];
    const float* pw_b1  = (const float*)d_in[12];
    const float* pw_w2  = (const float*)d_in[13];
    const float* pw_c2b = (const float*)d_in[14];
    const float* sn_w0  = (const float*)d_in[15];
    const float* sn_g0  = (const float*)d_in[16];
    const float* sn_b0  = (const float*)d_in[17];
    const float* sn_w1  = (const float*)d_in[18];
    const float* sn_g1  = (const float*)d_in[19];
    const float* sn_b1  = (const float*)d_in[20];
    const float* sn_w2  = (const float*)d_in[21];
    const float* sn_c2b = (const float*)d_in[22];
    const int*   is_inv = (const int*)d_in[23];

    float* out       = (float*)d_out;
    float* out_depth = out;
    float* out_score = out + (size_t)BB*HWP;
    float* out_vw    = out + (size_t)BB*HWP + (size_t)BB*DD*HWP;

    k_transpose<<<dim3(HWP/64, VV*BB + BB), 256>>>(ref_feature, src_features);
    k_proj<<<1, 32>>>(ref_proj, src_projs);
    k_main<<<BB*HWP/16, 128>>>(depth_sample,
                               pw_w0, pw_g0, pw_b0, pw_w1, pw_g1, pw_b1, pw_w2, pw_c2b,
                               sn_w0, sn_g0, sn_b0, sn_w1, sn_g1, sn_b1, sn_w2, sn_c2b,
                               out_vw);
    k_final<<<(BB*HWP*4 + 127)/128, 128>>>(grid, weight, depth_sample, is_inv,
                                           out_depth, out_score);
}